// round 1
// baseline (speedup 1.0000x reference)
#include <cuda_runtime.h>
#include <cuda_bf16.h>
#include <math.h>

// ---------------------------------------------------------------------------
// NanoGPT forward (fp32 baseline).
//   z = encoder[x]; 6x transformer block (shared params); logits = z @ enc^T;
//   loss = mean NLL.  Faithful to reference's buggy LN: (x - mu/sqrt(var))*g+b,
//   var with ddof=1.
// ---------------------------------------------------------------------------

#define D_MODEL 1024
#define SEQ_T   1024
#define BATCH   4
#define ROWS    (BATCH * SEQ_T)       // 4096 token rows
#define VOCAB   32000
#define NLAYERS 6
#define LOGITS_ELEMS ((long long)ROWS * VOCAB)   // 131,072,000

// ---- scratch (device globals; allocation-free kernel_launch) ----
__device__ float g_z[ROWS * D_MODEL];
__device__ float g_y[ROWS * D_MODEL];
__device__ float g_q[ROWS * D_MODEL];
__device__ float g_k[ROWS * D_MODEL];
__device__ float g_v[ROWS * D_MODEL];
__device__ float g_s[BATCH * SEQ_T * SEQ_T];
__device__ float g_h[ROWS * D_MODEL];
__device__ float g_o[ROWS * D_MODEL];
__device__ float g_nll[ROWS];

// ---------------------------------------------------------------------------
// SGEMM: C[M,N] = alpha * A[M,K] @ op(B) (+bias) (+res) (relu?)
//   TB=false : B is K x N row-major
//   TB=true  : B is N x K row-major  (C = A @ B^T)
// Tiles: BM=BN=128, BK=8; 256 threads; 8x8 per thread.
// All dims assumed multiples of the tile sizes (true for this problem).
// blockIdx.z batches with element strides sA, sB, sC.
// ---------------------------------------------------------------------------
template <bool TB, bool BIAS, bool RELU, bool RES>
__global__ __launch_bounds__(256)
void sgemm(const float* __restrict__ A, const float* __restrict__ B,
           float* __restrict__ C, const float* __restrict__ bias,
           const float* __restrict__ res,
           int M, int N, int K, float alpha,
           long long sA, long long sB, long long sC)
{
    A += (long long)blockIdx.z * sA;
    B += (long long)blockIdx.z * sB;
    C += (long long)blockIdx.z * sC;
    const float* resp = RES ? (res + (long long)blockIdx.z * sC) : nullptr;

    __shared__ float As[8][128];
    __shared__ float Bs[8][128];

    const int tid = threadIdx.x;
    const int m0 = blockIdx.y * 128;
    const int n0 = blockIdx.x * 128;

    const int arow = tid >> 1;            // 0..127
    const int akg  = (tid & 1) * 4;       // 0 or 4

    const int ty = tid >> 4;              // 0..15 -> row group
    const int tx = tid & 15;              // 0..15 -> col group

    float acc[8][8];
#pragma unroll
    for (int i = 0; i < 8; ++i)
#pragma unroll
        for (int j = 0; j < 8; ++j) acc[i][j] = 0.f;

    for (int k0 = 0; k0 < K; k0 += 8) {
        // ---- load A tile (BMxBK), store transposed ----
        float4 a4 = *(const float4*)(A + (long long)(m0 + arow) * K + k0 + akg);
        As[akg + 0][arow] = a4.x;
        As[akg + 1][arow] = a4.y;
        As[akg + 2][arow] = a4.z;
        As[akg + 3][arow] = a4.w;
        // ---- load B tile ----
        if (!TB) {
            int bk = tid >> 5;            // 0..7
            int bn = (tid & 31) * 4;      // 0..124
            float4 b4 = *(const float4*)(B + (long long)(k0 + bk) * N + n0 + bn);
            *(float4*)&Bs[bk][bn] = b4;
        } else {
            int bn = tid >> 1;            // 0..127
            int bk = (tid & 1) * 4;       // 0 or 4
            float4 b4 = *(const float4*)(B + (long long)(n0 + bn) * K + k0 + bk);
            Bs[bk + 0][bn] = b4.x;
            Bs[bk + 1][bn] = b4.y;
            Bs[bk + 2][bn] = b4.z;
            Bs[bk + 3][bn] = b4.w;
        }
        __syncthreads();
#pragma unroll
        for (int k = 0; k < 8; ++k) {
            float ra[8], rb[8];
            *(float4*)&ra[0] = *(const float4*)&As[k][ty * 8];
            *(float4*)&ra[4] = *(const float4*)&As[k][ty * 8 + 4];
            *(float4*)&rb[0] = *(const float4*)&Bs[k][tx * 8];
            *(float4*)&rb[4] = *(const float4*)&Bs[k][tx * 8 + 4];
#pragma unroll
            for (int i = 0; i < 8; ++i)
#pragma unroll
                for (int j = 0; j < 8; ++j)
                    acc[i][j] = fmaf(ra[i], rb[j], acc[i][j]);
        }
        __syncthreads();
    }

    // ---- epilogue ----
#pragma unroll
    for (int i = 0; i < 8; ++i) {
        const int m = m0 + ty * 8 + i;
        float* crow = C + (long long)m * N + n0 + tx * 8;
        const float* rrow = RES ? (resp + (long long)m * N + n0 + tx * 8) : nullptr;
#pragma unroll
        for (int jv = 0; jv < 2; ++jv) {
            float4 o;
            float t[4];
#pragma unroll
            for (int j = 0; j < 4; ++j) {
                float v = acc[i][jv * 4 + j] * alpha;
                if (BIAS) v += bias[n0 + tx * 8 + jv * 4 + j];
                if (RELU) v = fmaxf(v, 0.f);
                if (RES)  v += rrow[jv * 4 + j];
                t[j] = v;
            }
            o.x = t[0]; o.y = t[1]; o.z = t[2]; o.w = t[3];
            *(float4*)(crow + jv * 4) = o;
        }
    }
}

// ---------------------------------------------------------------------------
// Embedding gather: z[row,:] = encoder[x[row],:]
// ---------------------------------------------------------------------------
__global__ __launch_bounds__(256)
void embed_kernel(const int* __restrict__ x, const float* __restrict__ enc,
                  float* __restrict__ z)
{
    const int row = blockIdx.x;
    const long long src = (long long)x[row] * D_MODEL;
    const long long dst = (long long)row * D_MODEL;
    const float4* s = (const float4*)(enc + src);
    float4* d = (float4*)(z + dst);
    d[threadIdx.x] = s[threadIdx.x];     // 256 * float4 = 1024 floats
}

// ---------------------------------------------------------------------------
// "LayerNorm" (buggy per reference): y = (x - mu/sqrt(var)) * g + b, ddof=1
// One block per row of 1024.
// ---------------------------------------------------------------------------
__global__ __launch_bounds__(256)
void ln_kernel(const float* __restrict__ x, float* __restrict__ y,
               const float* __restrict__ g, const float* __restrict__ b)
{
    const int row = blockIdx.x;
    const float* xr = x + (long long)row * D_MODEL;
    float* yr = y + (long long)row * D_MODEL;

    float v[4];
    float s = 0.f, s2 = 0.f;
#pragma unroll
    for (int u = 0; u < 4; ++u) {
        v[u] = xr[threadIdx.x + u * 256];
        s += v[u];
        s2 += v[u] * v[u];
    }
#pragma unroll
    for (int o = 16; o; o >>= 1) {
        s  += __shfl_down_sync(0xffffffffu, s, o);
        s2 += __shfl_down_sync(0xffffffffu, s2, o);
    }
    __shared__ float shs[8], shs2[8], shsub;
    const int w = threadIdx.x >> 5, l = threadIdx.x & 31;
    if (l == 0) { shs[w] = s; shs2[w] = s2; }
    __syncthreads();
    if (threadIdx.x == 0) {
        float ts = 0.f, ts2 = 0.f;
#pragma unroll
        for (int i = 0; i < 8; ++i) { ts += shs[i]; ts2 += shs2[i]; }
        const float mu  = ts / (float)D_MODEL;
        const float var = (ts2 - (float)D_MODEL * mu * mu) / (float)(D_MODEL - 1);
        shsub = mu * rsqrtf(var);        // mu / sqrt(var)
    }
    __syncthreads();
    const float sub = shsub;
#pragma unroll
    for (int u = 0; u < 4; ++u) {
        const int i = threadIdx.x + u * 256;
        yr[i] = (v[u] - sub) * g[i] + b[i];
    }
}

// ---------------------------------------------------------------------------
// Row softmax over T=1024. In-place on s.
// ---------------------------------------------------------------------------
__global__ __launch_bounds__(256)
void softmax_kernel(float* __restrict__ s)
{
    float* r = s + (long long)blockIdx.x * SEQ_T;
    float v[4];
    float m = -1e30f;
#pragma unroll
    for (int u = 0; u < 4; ++u) { v[u] = r[threadIdx.x + u * 256]; m = fmaxf(m, v[u]); }
#pragma unroll
    for (int o = 16; o; o >>= 1) m = fmaxf(m, __shfl_down_sync(0xffffffffu, m, o));
    __shared__ float shm[8], shsum[8], shM, shS;
    const int w = threadIdx.x >> 5, l = threadIdx.x & 31;
    if (l == 0) shm[w] = m;
    __syncthreads();
    if (threadIdx.x == 0) {
        float t = shm[0];
#pragma unroll
        for (int i = 1; i < 8; ++i) t = fmaxf(t, shm[i]);
        shM = t;
    }
    __syncthreads();
    const float M = shM;
    float sum = 0.f;
#pragma unroll
    for (int u = 0; u < 4; ++u) { v[u] = __expf(v[u] - M); sum += v[u]; }
#pragma unroll
    for (int o = 16; o; o >>= 1) sum += __shfl_down_sync(0xffffffffu, sum, o);
    if (l == 0) shsum[w] = sum;
    __syncthreads();
    if (threadIdx.x == 0) {
        float t = 0.f;
#pragma unroll
        for (int i = 0; i < 8; ++i) t += shsum[i];
        shS = 1.f / t;
    }
    __syncthreads();
    const float inv = shS;
#pragma unroll
    for (int u = 0; u < 4; ++u) r[threadIdx.x + u * 256] = v[u] * inv;
}

// ---------------------------------------------------------------------------
// Per-row NLL from logits: nll[row] = logsumexp(row) - row[y[row]]
// ---------------------------------------------------------------------------
__global__ __launch_bounds__(256)
void nll_kernel(const float* __restrict__ logits, const int* __restrict__ y,
                float* __restrict__ nll)
{
    const int row = blockIdx.x;
    const float* r = logits + (long long)row * VOCAB;
    float m = -1e30f;
    for (int i = threadIdx.x; i < VOCAB; i += 256) m = fmaxf(m, r[i]);
#pragma unroll
    for (int o = 16; o; o >>= 1) m = fmaxf(m, __shfl_down_sync(0xffffffffu, m, o));
    __shared__ float shm[8], shsum[8], shM;
    const int w = threadIdx.x >> 5, l = threadIdx.x & 31;
    if (l == 0) shm[w] = m;
    __syncthreads();
    if (threadIdx.x == 0) {
        float t = shm[0];
#pragma unroll
        for (int i = 1; i < 8; ++i) t = fmaxf(t, shm[i]);
        shM = t;
    }
    __syncthreads();
    const float M = shM;
    float sum = 0.f;
    for (int i = threadIdx.x; i < VOCAB; i += 256) sum += __expf(r[i] - M);
#pragma unroll
    for (int o = 16; o; o >>= 1) sum += __shfl_down_sync(0xffffffffu, sum, o);
    if (l == 0) shsum[w] = sum;
    __syncthreads();
    if (threadIdx.x == 0) {
        float t = 0.f;
#pragma unroll
        for (int i = 0; i < 8; ++i) t += shsum[i];
        nll[row] = logf(t) + M - r[y[row]];
    }
}

// Deterministic final mean over 4096 rows -> optional loss slot at end of out.
__global__ __launch_bounds__(256)
void loss_kernel(const float* __restrict__ nll, float* __restrict__ out,
                 long long out_elems)
{
    __shared__ float sh[256];
    float s = 0.f;
#pragma unroll
    for (int u = 0; u < ROWS / 256; ++u) s += nll[threadIdx.x + u * 256];
    sh[threadIdx.x] = s;
    __syncthreads();
    for (int stride = 128; stride > 0; stride >>= 1) {
        if (threadIdx.x < stride) sh[threadIdx.x] += sh[threadIdx.x + stride];
        __syncthreads();
    }
    if (threadIdx.x == 0 && out_elems > LOGITS_ELEMS)
        out[LOGITS_ELEMS] = sh[0] / (float)ROWS;
}

// ---------------------------------------------------------------------------
extern "C" void kernel_launch(void* const* d_in, const int* in_sizes, int n_in,
                              void* d_out, int out_size)
{
    const int*   x   = (const int*)  d_in[0];
    const int*   ytk = (const int*)  d_in[1];
    const float* enc = (const float*)d_in[2];
    const float* g1  = (const float*)d_in[3];
    const float* b1  = (const float*)d_in[4];
    const float* wq  = (const float*)d_in[5];
    const float* wk  = (const float*)d_in[6];
    const float* wv  = (const float*)d_in[7];
    const float* g2  = (const float*)d_in[8];
    const float* b2  = (const float*)d_in[9];
    const float* w1  = (const float*)d_in[10];
    const float* bb1 = (const float*)d_in[11];
    const float* w2  = (const float*)d_in[12];
    const float* bb2 = (const float*)d_in[13];
    float* out = (float*)d_out;

    float *z, *y, *q, *k, *v, *s, *h, *o, *nll;
    cudaGetSymbolAddress((void**)&z,   g_z);
    cudaGetSymbolAddress((void**)&y,   g_y);
    cudaGetSymbolAddress((void**)&q,   g_q);
    cudaGetSymbolAddress((void**)&k,   g_k);
    cudaGetSymbolAddress((void**)&v,   g_v);
    cudaGetSymbolAddress((void**)&s,   g_s);
    cudaGetSymbolAddress((void**)&h,   g_h);
    cudaGetSymbolAddress((void**)&o,   g_o);
    cudaGetSymbolAddress((void**)&nll, g_nll);

    const long long TD = (long long)SEQ_T * D_MODEL;
    const long long TT = (long long)SEQ_T * SEQ_T;
    const float attn_scale = 1.f / 32.f;   // 1/sqrt(1024)

    embed_kernel<<<ROWS, 256>>>(x, enc, z);

    const dim3 gMain(D_MODEL / 128, ROWS / 128);       // (8, 32)
    const dim3 gAttn(SEQ_T / 128, SEQ_T / 128, BATCH); // (8, 8, 4)

    for (int layer = 0; layer < NLAYERS; ++layer) {
        ln_kernel<<<ROWS, 256>>>(z, y, g1, b1);
        sgemm<false, false, false, false><<<gMain, 256>>>(
            y, wq, q, nullptr, nullptr, ROWS, D_MODEL, D_MODEL, 1.f, 0, 0, 0);
        sgemm<false, false, false, false><<<gMain, 256>>>(
            y, wk, k, nullptr, nullptr, ROWS, D_MODEL, D_MODEL, 1.f, 0, 0, 0);
        sgemm<false, false, false, false><<<gMain, 256>>>(
            y, wv, v, nullptr, nullptr, ROWS, D_MODEL, D_MODEL, 1.f, 0, 0, 0);
        // s = softmax(q k^T / 32) per batch
        sgemm<true, false, false, false><<<gAttn, 256>>>(
            q, k, s, nullptr, nullptr, SEQ_T, SEQ_T, D_MODEL, attn_scale, TD, TD, TT);
        softmax_kernel<<<ROWS, 256>>>(s);
        // o = s @ v per batch
        sgemm<false, false, false, false><<<gAttn, 256>>>(
            s, v, o, nullptr, nullptr, SEQ_T, D_MODEL, SEQ_T, 1.f, TT, TD, TD);
        ln_kernel<<<ROWS, 256>>>(o, y, g2, b2);
        // h = relu(y @ w1 + bb1)
        sgemm<false, true, true, false><<<gMain, 256>>>(
            y, w1, h, bb1, nullptr, ROWS, D_MODEL, D_MODEL, 1.f, 0, 0, 0);
        // z = z + (h @ w2 + bb2)
        sgemm<false, true, false, true><<<gMain, 256>>>(
            h, w2, z, bb2, z, ROWS, D_MODEL, D_MODEL, 1.f, 0, 0, 0);
    }

    // logits = z @ enc^T  (4096 x 32000, K=1024)
    const dim3 gLog(VOCAB / 128, ROWS / 128);          // (250, 32)
    sgemm<true, false, false, false><<<gLog, 256>>>(
        z, enc, out, nullptr, nullptr, ROWS, VOCAB, D_MODEL, 1.f, 0, 0, 0);

    nll_kernel<<<ROWS, 256>>>(out, ytk, nll);
    loss_kernel<<<1, 256>>>(nll, out, (long long)out_size);
}

// round 2
// speedup vs baseline: 2.6877x; 2.6877x over previous
#include <cuda_runtime.h>
#include <cuda_bf16.h>
#include <math.h>
#include <stdint.h>

// ---------------------------------------------------------------------------
// NanoGPT forward — round 2: all GEMMs on tensor pipe via mma.sync tf32.
// ---------------------------------------------------------------------------

#define D_MODEL 1024
#define SEQ_T   1024
#define BATCH   4
#define ROWS    (BATCH * SEQ_T)
#define VOCAB   32000
#define NLAYERS 6
#define LOGITS_ELEMS ((long long)ROWS * VOCAB)

// ---- scratch ----
__device__ float g_z[ROWS * D_MODEL];
__device__ float g_y[ROWS * D_MODEL];
__device__ float g_q[ROWS * D_MODEL];
__device__ float g_k[ROWS * D_MODEL];
__device__ float g_v[ROWS * D_MODEL];
__device__ float g_s[BATCH * SEQ_T * SEQ_T];
__device__ float g_h[ROWS * D_MODEL];
__device__ float g_o[ROWS * D_MODEL];
__device__ float g_nll[ROWS];

__device__ __forceinline__ uint32_t f2tf(float x) {
    uint32_t u;
    asm("cvt.rna.tf32.f32 %0, %1;" : "=r"(u) : "f"(x));
    return u;
}

__device__ __forceinline__ void mma_tf32(float c[4], const uint32_t a[4],
                                         const uint32_t b[2]) {
    asm volatile(
        "mma.sync.aligned.m16n8k8.row.col.f32.tf32.tf32.f32 "
        "{%0,%1,%2,%3}, {%4,%5,%6,%7}, {%8,%9}, {%0,%1,%2,%3};\n"
        : "+f"(c[0]), "+f"(c[1]), "+f"(c[2]), "+f"(c[3])
        : "r"(a[0]), "r"(a[1]), "r"(a[2]), "r"(a[3]), "r"(b[0]), "r"(b[1]));
}

// ---------------------------------------------------------------------------
// Tensor-core GEMM: C[M,N] = alpha * A[M,K] @ op(B) (+bias)(relu)(+res)
//   TB=false: B is KxN row-major.  TB=true: B is NxK row-major (C = A B^T).
// Block 128x128x32, 256 threads, warp tile 64x32 (warps 2m x 4n).
// Smem: As[m][k] stride 36 (conflict-free), Bs: NT -> [n][k] stride 36,
//       NN -> [k][n] stride 132. Register-staged gmem prefetch.
// All dims multiples of tile sizes (holds for this problem).
// ---------------------------------------------------------------------------
template <bool TB, bool BIAS, bool RELU, bool RES>
__global__ __launch_bounds__(256)
void tgemm(const float* __restrict__ A, const float* __restrict__ B,
           float* __restrict__ C, const float* __restrict__ bias,
           const float* __restrict__ res,
           int M, int N, int K, float alpha,
           long long sA, long long sB, long long sC)
{
    A += (long long)blockIdx.z * sA;
    B += (long long)blockIdx.z * sB;
    C += (long long)blockIdx.z * sC;
    const float* resp = RES ? (res + (long long)blockIdx.z * sC) : nullptr;

    __shared__ uint32_t As[128 * 36];
    __shared__ uint32_t Bs[4608];   // max(128*36, 32*132)

    const int tid  = threadIdx.x;
    const int lane = tid & 31;
    const int warp = tid >> 5;
    const int wm   = (warp & 1) * 64;   // warp m offset
    const int wn   = (warp >> 1) * 32;  // warp n offset
    const int q    = lane & 3;
    const int g    = lane >> 2;
    const long long m0 = (long long)blockIdx.y * 128;
    const long long n0 = (long long)blockIdx.x * 128;

    // staging index maps (coalesced float4 loads)
    const int arow = tid >> 3;          // + 32*s  (A rows / TB-B rows)
    const int akq  = (tid & 7) * 4;     // k offset
    const int bk   = tid >> 5;          // + 8*s   (NN-B k rows)
    const int bn4  = (tid & 31) * 4;    // n offset

    float4 ra[4], rb[4];

    float acc[4][4][4];
#pragma unroll
    for (int mt = 0; mt < 4; ++mt)
#pragma unroll
        for (int nt = 0; nt < 4; ++nt)
#pragma unroll
            for (int i = 0; i < 4; ++i) acc[mt][nt][i] = 0.f;

    auto LDG = [&](int k0) {
#pragma unroll
        for (int s = 0; s < 4; ++s)
            ra[s] = *(const float4*)(A + (m0 + arow + 32 * s) * K + k0 + akq);
        if (TB) {
#pragma unroll
            for (int s = 0; s < 4; ++s)
                rb[s] = *(const float4*)(B + (n0 + arow + 32 * s) * K + k0 + akq);
        } else {
#pragma unroll
            for (int s = 0; s < 4; ++s)
                rb[s] = *(const float4*)(B + (long long)(k0 + bk + 8 * s) * N + n0 + bn4);
        }
    };

    auto STS = [&]() {
#pragma unroll
        for (int s = 0; s < 4; ++s) {
            uint32_t* p = &As[(arow + 32 * s) * 36 + akq];
            p[0] = f2tf(ra[s].x); p[1] = f2tf(ra[s].y);
            p[2] = f2tf(ra[s].z); p[3] = f2tf(ra[s].w);
        }
        if (TB) {
#pragma unroll
            for (int s = 0; s < 4; ++s) {
                uint32_t* p = &Bs[(arow + 32 * s) * 36 + akq];
                p[0] = f2tf(rb[s].x); p[1] = f2tf(rb[s].y);
                p[2] = f2tf(rb[s].z); p[3] = f2tf(rb[s].w);
            }
        } else {
#pragma unroll
            for (int s = 0; s < 4; ++s) {
                uint32_t* p = &Bs[(bk + 8 * s) * 132 + bn4];
                p[0] = f2tf(rb[s].x); p[1] = f2tf(rb[s].y);
                p[2] = f2tf(rb[s].z); p[3] = f2tf(rb[s].w);
            }
        }
    };

    auto COMP = [&]() {
#pragma unroll
        for (int kb = 0; kb < 32; kb += 8) {
            uint32_t af[4][4], bf[4][2];
#pragma unroll
            for (int mt = 0; mt < 4; ++mt) {
                const int mr = wm + mt * 16 + g;
                af[mt][0] = As[mr * 36 + kb + q];
                af[mt][1] = As[(mr + 8) * 36 + kb + q];
                af[mt][2] = As[mr * 36 + kb + q + 4];
                af[mt][3] = As[(mr + 8) * 36 + kb + q + 4];
            }
#pragma unroll
            for (int nt = 0; nt < 4; ++nt) {
                const int nr = wn + nt * 8 + g;
                if (TB) {
                    bf[nt][0] = Bs[nr * 36 + kb + q];
                    bf[nt][1] = Bs[nr * 36 + kb + q + 4];
                } else {
                    bf[nt][0] = Bs[(kb + q) * 132 + nr];
                    bf[nt][1] = Bs[(kb + q + 4) * 132 + nr];
                }
            }
#pragma unroll
            for (int mt = 0; mt < 4; ++mt)
#pragma unroll
                for (int nt = 0; nt < 4; ++nt)
                    mma_tf32(acc[mt][nt], af[mt], bf[nt]);
        }
    };

    LDG(0);
    STS();
    __syncthreads();
    for (int k0 = 32;; k0 += 32) {
        const bool more = (k0 < K);
        if (more) LDG(k0);
        COMP();
        if (!more) break;
        __syncthreads();
        STS();
        __syncthreads();
    }

    // ---- epilogue ----
#pragma unroll
    for (int mt = 0; mt < 4; ++mt) {
        const long long r0 = m0 + wm + mt * 16 + g;
        const long long r1 = r0 + 8;
#pragma unroll
        for (int nt = 0; nt < 4; ++nt) {
            const long long col = n0 + wn + nt * 8 + 2 * q;
            float v0 = acc[mt][nt][0] * alpha;
            float v1 = acc[mt][nt][1] * alpha;
            float v2 = acc[mt][nt][2] * alpha;
            float v3 = acc[mt][nt][3] * alpha;
            if (BIAS) {
                const float bb0 = bias[col], bb1 = bias[col + 1];
                v0 += bb0; v1 += bb1; v2 += bb0; v3 += bb1;
            }
            if (RELU) {
                v0 = fmaxf(v0, 0.f); v1 = fmaxf(v1, 0.f);
                v2 = fmaxf(v2, 0.f); v3 = fmaxf(v3, 0.f);
            }
            if (RES) {
                const float2 q0 = *(const float2*)(resp + r0 * N + col);
                const float2 q1 = *(const float2*)(resp + r1 * N + col);
                v0 += q0.x; v1 += q0.y; v2 += q1.x; v3 += q1.y;
            }
            *(float2*)(C + r0 * N + col) = make_float2(v0, v1);
            *(float2*)(C + r1 * N + col) = make_float2(v2, v3);
        }
    }
}

// ---------------------------------------------------------------------------
// Embedding gather
// ---------------------------------------------------------------------------
__global__ __launch_bounds__(256)
void embed_kernel(const int* __restrict__ x, const float* __restrict__ enc,
                  float* __restrict__ z)
{
    const int row = blockIdx.x;
    const long long src = (long long)x[row] * D_MODEL;
    const long long dst = (long long)row * D_MODEL;
    const float4* s = (const float4*)(enc + src);
    float4* d = (float4*)(z + dst);
    d[threadIdx.x] = s[threadIdx.x];
}

// ---------------------------------------------------------------------------
// "LayerNorm" (faithful buggy): y = (x - mu/sqrt(var)) * g + b, ddof=1
// ---------------------------------------------------------------------------
__global__ __launch_bounds__(256)
void ln_kernel(const float* __restrict__ x, float* __restrict__ y,
               const float* __restrict__ g, const float* __restrict__ b)
{
    const int row = blockIdx.x;
    const float* xr = x + (long long)row * D_MODEL;
    float* yr = y + (long long)row * D_MODEL;

    float v[4];
    float s = 0.f, s2 = 0.f;
#pragma unroll
    for (int u = 0; u < 4; ++u) {
        v[u] = xr[threadIdx.x + u * 256];
        s += v[u];
        s2 += v[u] * v[u];
    }
#pragma unroll
    for (int o = 16; o; o >>= 1) {
        s  += __shfl_down_sync(0xffffffffu, s, o);
        s2 += __shfl_down_sync(0xffffffffu, s2, o);
    }
    __shared__ float shs[8], shs2[8], shsub;
    const int w = threadIdx.x >> 5, l = threadIdx.x & 31;
    if (l == 0) { shs[w] = s; shs2[w] = s2; }
    __syncthreads();
    if (threadIdx.x == 0) {
        float ts = 0.f, ts2 = 0.f;
#pragma unroll
        for (int i = 0; i < 8; ++i) { ts += shs[i]; ts2 += shs2[i]; }
        const float mu  = ts / (float)D_MODEL;
        const float var = (ts2 - (float)D_MODEL * mu * mu) / (float)(D_MODEL - 1);
        shsub = mu * rsqrtf(var);
    }
    __syncthreads();
    const float sub = shsub;
#pragma unroll
    for (int u = 0; u < 4; ++u) {
        const int i = threadIdx.x + u * 256;
        yr[i] = (v[u] - sub) * g[i] + b[i];
    }
}

// ---------------------------------------------------------------------------
// Row softmax over T=1024, in place
// ---------------------------------------------------------------------------
__global__ __launch_bounds__(256)
void softmax_kernel(float* __restrict__ s)
{
    float* r = s + (long long)blockIdx.x * SEQ_T;
    float v[4];
    float m = -1e30f;
#pragma unroll
    for (int u = 0; u < 4; ++u) { v[u] = r[threadIdx.x + u * 256]; m = fmaxf(m, v[u]); }
#pragma unroll
    for (int o = 16; o; o >>= 1) m = fmaxf(m, __shfl_down_sync(0xffffffffu, m, o));
    __shared__ float shm[8], shsum[8], shM, shS;
    const int w = threadIdx.x >> 5, l = threadIdx.x & 31;
    if (l == 0) shm[w] = m;
    __syncthreads();
    if (threadIdx.x == 0) {
        float t = shm[0];
#pragma unroll
        for (int i = 1; i < 8; ++i) t = fmaxf(t, shm[i]);
        shM = t;
    }
    __syncthreads();
    const float M = shM;
    float sum = 0.f;
#pragma unroll
    for (int u = 0; u < 4; ++u) { v[u] = __expf(v[u] - M); sum += v[u]; }
#pragma unroll
    for (int o = 16; o; o >>= 1) sum += __shfl_down_sync(0xffffffffu, sum, o);
    if (l == 0) shsum[w] = sum;
    __syncthreads();
    if (threadIdx.x == 0) {
        float t = 0.f;
#pragma unroll
        for (int i = 0; i < 8; ++i) t += shsum[i];
        shS = 1.f / t;
    }
    __syncthreads();
    const float inv = shS;
#pragma unroll
    for (int u = 0; u < 4; ++u) r[threadIdx.x + u * 256] = v[u] * inv;
}

// ---------------------------------------------------------------------------
// Per-row NLL
// ---------------------------------------------------------------------------
__global__ __launch_bounds__(256)
void nll_kernel(const float* __restrict__ logits, const int* __restrict__ y,
                float* __restrict__ nll)
{
    const int row = blockIdx.x;
    const float* r = logits + (long long)row * VOCAB;
    float m = -1e30f;
    for (int i = threadIdx.x; i < VOCAB; i += 256) m = fmaxf(m, r[i]);
#pragma unroll
    for (int o = 16; o; o >>= 1) m = fmaxf(m, __shfl_down_sync(0xffffffffu, m, o));
    __shared__ float shm[8], shsum[8], shM;
    const int w = threadIdx.x >> 5, l = threadIdx.x & 31;
    if (l == 0) shm[w] = m;
    __syncthreads();
    if (threadIdx.x == 0) {
        float t = shm[0];
#pragma unroll
        for (int i = 1; i < 8; ++i) t = fmaxf(t, shm[i]);
        shM = t;
    }
    __syncthreads();
    const float M = shM;
    float sum = 0.f;
    for (int i = threadIdx.x; i < VOCAB; i += 256) sum += __expf(r[i] - M);
#pragma unroll
    for (int o = 16; o; o >>= 1) sum += __shfl_down_sync(0xffffffffu, sum, o);
    if (l == 0) shsum[w] = sum;
    __syncthreads();
    if (threadIdx.x == 0) {
        float t = 0.f;
#pragma unroll
        for (int i = 0; i < 8; ++i) t += shsum[i];
        nll[row] = logf(t) + M - r[y[row]];
    }
}

__global__ __launch_bounds__(256)
void loss_kernel(const float* __restrict__ nll, float* __restrict__ out,
                 long long out_elems)
{
    __shared__ float sh[256];
    float s = 0.f;
#pragma unroll
    for (int u = 0; u < ROWS / 256; ++u) s += nll[threadIdx.x + u * 256];
    sh[threadIdx.x] = s;
    __syncthreads();
    for (int stride = 128; stride > 0; stride >>= 1) {
        if (threadIdx.x < stride) sh[threadIdx.x] += sh[threadIdx.x + stride];
        __syncthreads();
    }
    if (threadIdx.x == 0 && out_elems > LOGITS_ELEMS)
        out[LOGITS_ELEMS] = sh[0] / (float)ROWS;
}

// ---------------------------------------------------------------------------
extern "C" void kernel_launch(void* const* d_in, const int* in_sizes, int n_in,
                              void* d_out, int out_size)
{
    const int*   x   = (const int*)  d_in[0];
    const int*   ytk = (const int*)  d_in[1];
    const float* enc = (const float*)d_in[2];
    const float* g1  = (const float*)d_in[3];
    const float* b1  = (const float*)d_in[4];
    const float* wq  = (const float*)d_in[5];
    const float* wk  = (const float*)d_in[6];
    const float* wv  = (const float*)d_in[7];
    const float* g2  = (const float*)d_in[8];
    const float* b2  = (const float*)d_in[9];
    const float* w1  = (const float*)d_in[10];
    const float* bb1 = (const float*)d_in[11];
    const float* w2  = (const float*)d_in[12];
    const float* bb2 = (const float*)d_in[13];
    float* out = (float*)d_out;

    float *z, *y, *q, *k, *v, *s, *h, *o, *nll;
    cudaGetSymbolAddress((void**)&z,   g_z);
    cudaGetSymbolAddress((void**)&y,   g_y);
    cudaGetSymbolAddress((void**)&q,   g_q);
    cudaGetSymbolAddress((void**)&k,   g_k);
    cudaGetSymbolAddress((void**)&v,   g_v);
    cudaGetSymbolAddress((void**)&s,   g_s);
    cudaGetSymbolAddress((void**)&h,   g_h);
    cudaGetSymbolAddress((void**)&o,   g_o);
    cudaGetSymbolAddress((void**)&nll, g_nll);

    const long long TD = (long long)SEQ_T * D_MODEL;
    const long long TT = (long long)SEQ_T * SEQ_T;
    const float attn_scale = 1.f / 32.f;

    embed_kernel<<<ROWS, 256>>>(x, enc, z);

    const dim3 gMain(D_MODEL / 128, ROWS / 128);       // (8, 32)
    const dim3 gAttn(SEQ_T / 128, SEQ_T / 128, BATCH); // (8, 8, 4)

    for (int layer = 0; layer < NLAYERS; ++layer) {
        ln_kernel<<<ROWS, 256>>>(z, y, g1, b1);
        tgemm<false, false, false, false><<<gMain, 256>>>(
            y, wq, q, nullptr, nullptr, ROWS, D_MODEL, D_MODEL, 1.f, 0, 0, 0);
        tgemm<false, false, false, false><<<gMain, 256>>>(
            y, wk, k, nullptr, nullptr, ROWS, D_MODEL, D_MODEL, 1.f, 0, 0, 0);
        tgemm<false, false, false, false><<<gMain, 256>>>(
            y, wv, v, nullptr, nullptr, ROWS, D_MODEL, D_MODEL, 1.f, 0, 0, 0);
        tgemm<true, false, false, false><<<gAttn, 256>>>(
            q, k, s, nullptr, nullptr, SEQ_T, SEQ_T, D_MODEL, attn_scale, TD, TD, TT);
        softmax_kernel<<<ROWS, 256>>>(s);
        tgemm<false, false, false, false><<<gAttn, 256>>>(
            s, v, o, nullptr, nullptr, SEQ_T, D_MODEL, SEQ_T, 1.f, TT, TD, TD);
        ln_kernel<<<ROWS, 256>>>(o, y, g2, b2);
        tgemm<false, true, true, false><<<gMain, 256>>>(
            y, w1, h, bb1, nullptr, ROWS, D_MODEL, D_MODEL, 1.f, 0, 0, 0);
        tgemm<false, true, false, true><<<gMain, 256>>>(
            h, w2, z, bb2, z, ROWS, D_MODEL, D_MODEL, 1.f, 0, 0, 0);
    }

    const dim3 gLog(VOCAB / 128, ROWS / 128);          // (250, 32)
    tgemm<true, false, false, false><<<gLog, 256>>>(
        z, enc, out, nullptr, nullptr, ROWS, VOCAB, D_MODEL, 1.f, 0, 0, 0);

    nll_kernel<<<ROWS, 256>>>(out, ytk, nll);
    loss_kernel<<<1, 256>>>(nll, out, (long long)out_size);
}

// round 3
// speedup vs baseline: 3.4648x; 1.2892x over previous
#include <cuda_runtime.h>
#include <cuda_bf16.h>
#include <math.h>
#include <stdint.h>

// ---------------------------------------------------------------------------
// NanoGPT forward — round 3: tf32 mma.sync + cp.async double-buffer pipeline,
// pre-rounded operands (rna) so GEMMs stream raw bytes, 2 CTAs/SM.
// ---------------------------------------------------------------------------

#define D_MODEL 1024
#define SEQ_T   1024
#define BATCH   4
#define ROWS    (BATCH * SEQ_T)
#define VOCAB   32000
#define NLAYERS 6
#define LOGITS_ELEMS ((long long)ROWS * VOCAB)

// ---- scratch ----
__device__ float g_z[ROWS * D_MODEL];
__device__ float g_y[ROWS * D_MODEL];
__device__ float g_q[ROWS * D_MODEL];
__device__ float g_k[ROWS * D_MODEL];
__device__ float g_v[ROWS * D_MODEL];
__device__ float g_s[BATCH * SEQ_T * SEQ_T];
__device__ float g_h[ROWS * D_MODEL];
__device__ float g_o[ROWS * D_MODEL];
__device__ float g_nll[ROWS];
// rounded-operand copies
__device__ float g_wq_r[D_MODEL * D_MODEL];
__device__ float g_wk_r[D_MODEL * D_MODEL];
__device__ float g_wv_r[D_MODEL * D_MODEL];
__device__ float g_w1_r[D_MODEL * D_MODEL];
__device__ float g_w2_r[D_MODEL * D_MODEL];
__device__ float g_enc_r[(long long)VOCAB * D_MODEL];

__device__ __forceinline__ float rnd_tf32(float x) {
    uint32_t u;
    asm("cvt.rna.tf32.f32 %0, %1;" : "=r"(u) : "f"(x));
    return __uint_as_float(u);
}

__device__ __forceinline__ void mma_tf32(float c[4], const uint32_t a[4],
                                         const uint32_t b[2]) {
    asm volatile(
        "mma.sync.aligned.m16n8k8.row.col.f32.tf32.tf32.f32 "
        "{%0,%1,%2,%3}, {%4,%5,%6,%7}, {%8,%9}, {%0,%1,%2,%3};\n"
        : "+f"(c[0]), "+f"(c[1]), "+f"(c[2]), "+f"(c[3])
        : "r"(a[0]), "r"(a[1]), "r"(a[2]), "r"(a[3]), "r"(b[0]), "r"(b[1]));
}

__device__ __forceinline__ void cpa16(float* dst, const float* src) {
    uint32_t d = (uint32_t)__cvta_generic_to_shared(dst);
    asm volatile("cp.async.cg.shared.global [%0], [%1], 16;\n"
                 :: "r"(d), "l"(src));
}

// per-stage words: A 128*36=4608 + B 4608
#define STAGE_WORDS 9216
#define GEMM_SMEM_BYTES (2 * STAGE_WORDS * 4)

// ---------------------------------------------------------------------------
// Tensor-core GEMM (tf32 in / fp32 acc), inputs MUST be pre-rounded tf32.
//   TB=false: B is KxN row-major.  TB=true: B is NxK row-major (C = A B^T).
// Block 128x128x32, 256 threads, 8 warps (2m x 4n), warp tile 64x32.
// 2-stage cp.async pipeline; smem A[m][k] stride36, B NT [n][k] stride36,
// B NN [k][n] stride132.
// ---------------------------------------------------------------------------
template <bool TB, bool BIAS, bool RELU, bool RES, bool ROUND>
__global__ __launch_bounds__(256, 2)
void tgemm(const float* __restrict__ A, const float* __restrict__ B,
           float* __restrict__ C, const float* __restrict__ bias,
           const float* __restrict__ res,
           int M, int N, int K, float alpha,
           long long sA, long long sB, long long sC)
{
    extern __shared__ float smem[];

    A += (long long)blockIdx.z * sA;
    B += (long long)blockIdx.z * sB;
    C += (long long)blockIdx.z * sC;
    const float* resp = RES ? (res + (long long)blockIdx.z * sC) : nullptr;

    const int tid  = threadIdx.x;
    const int lane = tid & 31;
    const int warp = tid >> 5;
    const int wm   = (warp & 1) * 64;
    const int wn   = (warp >> 1) * 32;
    const int q    = lane & 3;
    const int g    = lane >> 2;
    const long long m0 = (long long)blockIdx.y * 128;
    const long long n0 = (long long)blockIdx.x * 128;

    const int arow = tid >> 3;          // +32*s
    const int ak4  = (tid & 7) * 4;
    const int bk   = tid >> 5;          // +8*s (NN)
    const int bn4  = (tid & 31) * 4;

    float acc[4][4][4];
#pragma unroll
    for (int mt = 0; mt < 4; ++mt)
#pragma unroll
        for (int nt = 0; nt < 4; ++nt)
#pragma unroll
            for (int i = 0; i < 4; ++i) acc[mt][nt][i] = 0.f;

    auto LOAD = [&](int stage, int k0) {
        float* As_ = smem + stage * STAGE_WORDS;
        float* Bs_ = As_ + 4608;
#pragma unroll
        for (int s = 0; s < 4; ++s)
            cpa16(&As_[(arow + 32 * s) * 36 + ak4],
                  A + (m0 + arow + 32 * s) * (long long)K + k0 + ak4);
        if (TB) {
#pragma unroll
            for (int s = 0; s < 4; ++s)
                cpa16(&Bs_[(arow + 32 * s) * 36 + ak4],
                      B + (n0 + arow + 32 * s) * (long long)K + k0 + ak4);
        } else {
#pragma unroll
            for (int s = 0; s < 4; ++s)
                cpa16(&Bs_[(bk + 8 * s) * 132 + bn4],
                      B + (long long)(k0 + bk + 8 * s) * N + n0 + bn4);
        }
    };

    auto COMP = [&](int stage) {
        const uint32_t* As_ = (const uint32_t*)(smem + stage * STAGE_WORDS);
        const uint32_t* Bs_ = As_ + 4608;
#pragma unroll
        for (int kb = 0; kb < 32; kb += 8) {
            uint32_t af[4][4], bf[4][2];
#pragma unroll
            for (int mt = 0; mt < 4; ++mt) {
                const int mr = wm + mt * 16 + g;
                af[mt][0] = As_[mr * 36 + kb + q];
                af[mt][1] = As_[(mr + 8) * 36 + kb + q];
                af[mt][2] = As_[mr * 36 + kb + q + 4];
                af[mt][3] = As_[(mr + 8) * 36 + kb + q + 4];
            }
#pragma unroll
            for (int nt = 0; nt < 4; ++nt) {
                const int nr = wn + nt * 8 + g;
                if (TB) {
                    bf[nt][0] = Bs_[nr * 36 + kb + q];
                    bf[nt][1] = Bs_[nr * 36 + kb + q + 4];
                } else {
                    bf[nt][0] = Bs_[(kb + q) * 132 + nr];
                    bf[nt][1] = Bs_[(kb + q + 4) * 132 + nr];
                }
            }
#pragma unroll
            for (int mt = 0; mt < 4; ++mt)
#pragma unroll
                for (int nt = 0; nt < 4; ++nt)
                    mma_tf32(acc[mt][nt], af[mt], bf[nt]);
        }
    };

    LOAD(0, 0);
    asm volatile("cp.async.commit_group;\n");
    const int T = K >> 5;
    for (int i = 0; i < T; ++i) {
        if (i + 1 < T) LOAD((i + 1) & 1, (i + 1) << 5);
        asm volatile("cp.async.commit_group;\n");
        asm volatile("cp.async.wait_group 1;\n");
        __syncthreads();
        COMP(i & 1);
        __syncthreads();
    }

    // ---- epilogue ----
#pragma unroll
    for (int mt = 0; mt < 4; ++mt) {
        const long long r0 = m0 + wm + mt * 16 + g;
        const long long r1 = r0 + 8;
#pragma unroll
        for (int nt = 0; nt < 4; ++nt) {
            const long long col = n0 + wn + nt * 8 + 2 * q;
            float v0 = acc[mt][nt][0] * alpha;
            float v1 = acc[mt][nt][1] * alpha;
            float v2 = acc[mt][nt][2] * alpha;
            float v3 = acc[mt][nt][3] * alpha;
            if (BIAS) {
                const float bb0 = bias[col], bb1 = bias[col + 1];
                v0 += bb0; v1 += bb1; v2 += bb0; v3 += bb1;
            }
            if (RELU) {
                v0 = fmaxf(v0, 0.f); v1 = fmaxf(v1, 0.f);
                v2 = fmaxf(v2, 0.f); v3 = fmaxf(v3, 0.f);
            }
            if (RES) {
                const float2 q0 = *(const float2*)(resp + r0 * N + col);
                const float2 q1 = *(const float2*)(resp + r1 * N + col);
                v0 += q0.x; v1 += q0.y; v2 += q1.x; v3 += q1.y;
            }
            if (ROUND) {
                v0 = rnd_tf32(v0); v1 = rnd_tf32(v1);
                v2 = rnd_tf32(v2); v3 = rnd_tf32(v3);
            }
            *(float2*)(C + r0 * N + col) = make_float2(v0, v1);
            *(float2*)(C + r1 * N + col) = make_float2(v2, v3);
        }
    }
}

// ---------------------------------------------------------------------------
// Elementwise tf32 rounding: out[i] = rna_tf32(in[i]); n multiple of 1024.
// ---------------------------------------------------------------------------
__global__ __launch_bounds__(256)
void round_kernel(const float* __restrict__ in, float* __restrict__ out)
{
    const long long i = ((long long)blockIdx.x * 256 + threadIdx.x) * 4;
    float4 v = *(const float4*)(in + i);
    v.x = rnd_tf32(v.x); v.y = rnd_tf32(v.y);
    v.z = rnd_tf32(v.z); v.w = rnd_tf32(v.w);
    *(float4*)(out + i) = v;
}

// ---------------------------------------------------------------------------
// Embedding gather (exact fp32 — residual stream stays unrounded)
// ---------------------------------------------------------------------------
__global__ __launch_bounds__(256)
void embed_kernel(const int* __restrict__ x, const float* __restrict__ enc,
                  float* __restrict__ z)
{
    const int row = blockIdx.x;
    const float4* s = (const float4*)(enc + (long long)x[row] * D_MODEL);
    float4* d = (float4*)(z + (long long)row * D_MODEL);
    d[threadIdx.x] = s[threadIdx.x];
}

// ---------------------------------------------------------------------------
// "LayerNorm" (faithful buggy): y = (x - mu/sqrt(var)) * g + b, ddof=1.
// Output rounded to tf32 (it only feeds GEMMs).
// ---------------------------------------------------------------------------
__global__ __launch_bounds__(256)
void ln_kernel(const float* __restrict__ x, float* __restrict__ y,
               const float* __restrict__ g, const float* __restrict__ b)
{
    const int row = blockIdx.x;
    const float* xr = x + (long long)row * D_MODEL;
    float* yr = y + (long long)row * D_MODEL;

    float v[4];
    float s = 0.f, s2 = 0.f;
#pragma unroll
    for (int u = 0; u < 4; ++u) {
        v[u] = xr[threadIdx.x + u * 256];
        s += v[u];
        s2 += v[u] * v[u];
    }
#pragma unroll
    for (int o = 16; o; o >>= 1) {
        s  += __shfl_down_sync(0xffffffffu, s, o);
        s2 += __shfl_down_sync(0xffffffffu, s2, o);
    }
    __shared__ float shs[8], shs2[8], shsub;
    const int w = threadIdx.x >> 5, l = threadIdx.x & 31;
    if (l == 0) { shs[w] = s; shs2[w] = s2; }
    __syncthreads();
    if (threadIdx.x == 0) {
        float ts = 0.f, ts2 = 0.f;
#pragma unroll
        for (int i = 0; i < 8; ++i) { ts += shs[i]; ts2 += shs2[i]; }
        const float mu  = ts / (float)D_MODEL;
        const float var = (ts2 - (float)D_MODEL * mu * mu) / (float)(D_MODEL - 1);
        shsub = mu * rsqrtf(var);
    }
    __syncthreads();
    const float sub = shsub;
#pragma unroll
    for (int u = 0; u < 4; ++u) {
        const int i = threadIdx.x + u * 256;
        yr[i] = rnd_tf32((v[u] - sub) * g[i] + b[i]);
    }
}

// ---------------------------------------------------------------------------
// Row softmax over T=1024, in place; output rounded (feeds AV GEMM only).
// ---------------------------------------------------------------------------
__global__ __launch_bounds__(256)
void softmax_kernel(float* __restrict__ s)
{
    float* r = s + (long long)blockIdx.x * SEQ_T;
    float v[4];
    float m = -1e30f;
#pragma unroll
    for (int u = 0; u < 4; ++u) { v[u] = r[threadIdx.x + u * 256]; m = fmaxf(m, v[u]); }
#pragma unroll
    for (int o = 16; o; o >>= 1) m = fmaxf(m, __shfl_down_sync(0xffffffffu, m, o));
    __shared__ float shm[8], shsum[8], shM, shS;
    const int w = threadIdx.x >> 5, l = threadIdx.x & 31;
    if (l == 0) shm[w] = m;
    __syncthreads();
    if (threadIdx.x == 0) {
        float t = shm[0];
#pragma unroll
        for (int i = 1; i < 8; ++i) t = fmaxf(t, shm[i]);
        shM = t;
    }
    __syncthreads();
    const float M = shM;
    float sum = 0.f;
#pragma unroll
    for (int u = 0; u < 4; ++u) { v[u] = __expf(v[u] - M); sum += v[u]; }
#pragma unroll
    for (int o = 16; o; o >>= 1) sum += __shfl_down_sync(0xffffffffu, sum, o);
    if (l == 0) shsum[w] = sum;
    __syncthreads();
    if (threadIdx.x == 0) {
        float t = 0.f;
#pragma unroll
        for (int i = 0; i < 8; ++i) t += shsum[i];
        shS = 1.f / t;
    }
    __syncthreads();
    const float inv = shS;
#pragma unroll
    for (int u = 0; u < 4; ++u)
        r[threadIdx.x + u * 256] = rnd_tf32(v[u] * inv);
}

// ---------------------------------------------------------------------------
// Per-row NLL
// ---------------------------------------------------------------------------
__global__ __launch_bounds__(256)
void nll_kernel(const float* __restrict__ logits, const int* __restrict__ y,
                float* __restrict__ nll)
{
    const int row = blockIdx.x;
    const float* r = logits + (long long)row * VOCAB;
    float m = -1e30f;
    for (int i = threadIdx.x; i < VOCAB; i += 256) m = fmaxf(m, r[i]);
#pragma unroll
    for (int o = 16; o; o >>= 1) m = fmaxf(m, __shfl_down_sync(0xffffffffu, m, o));
    __shared__ float shm[8], shsum[8], shM;
    const int w = threadIdx.x >> 5, l = threadIdx.x & 31;
    if (l == 0) shm[w] = m;
    __syncthreads();
    if (threadIdx.x == 0) {
        float t = shm[0];
#pragma unroll
        for (int i = 1; i < 8; ++i) t = fmaxf(t, shm[i]);
        shM = t;
    }
    __syncthreads();
    const float M = shM;
    float sum = 0.f;
    for (int i = threadIdx.x; i < VOCAB; i += 256) sum += __expf(r[i] - M);
#pragma unroll
    for (int o = 16; o; o >>= 1) sum += __shfl_down_sync(0xffffffffu, sum, o);
    if (l == 0) shsum[w] = sum;
    __syncthreads();
    if (threadIdx.x == 0) {
        float t = 0.f;
#pragma unroll
        for (int i = 0; i < 8; ++i) t += shsum[i];
        nll[row] = logf(t) + M - r[y[row]];
    }
}

__global__ __launch_bounds__(256)
void loss_kernel(const float* __restrict__ nll, float* __restrict__ out,
                 long long out_elems)
{
    __shared__ float sh[256];
    float s = 0.f;
#pragma unroll
    for (int u = 0; u < ROWS / 256; ++u) s += nll[threadIdx.x + u * 256];
    sh[threadIdx.x] = s;
    __syncthreads();
    for (int stride = 128; stride > 0; stride >>= 1) {
        if (threadIdx.x < stride) sh[threadIdx.x] += sh[threadIdx.x + stride];
        __syncthreads();
    }
    if (threadIdx.x == 0 && out_elems > LOGITS_ELEMS)
        out[LOGITS_ELEMS] = sh[0] / (float)ROWS;
}

// ---------------------------------------------------------------------------
extern "C" void kernel_launch(void* const* d_in, const int* in_sizes, int n_in,
                              void* d_out, int out_size)
{
    const int*   x   = (const int*)  d_in[0];
    const int*   ytk = (const int*)  d_in[1];
    const float* enc = (const float*)d_in[2];
    const float* g1  = (const float*)d_in[3];
    const float* b1  = (const float*)d_in[4];
    const float* wq  = (const float*)d_in[5];
    const float* wk  = (const float*)d_in[6];
    const float* wv  = (const float*)d_in[7];
    const float* g2  = (const float*)d_in[8];
    const float* b2  = (const float*)d_in[9];
    const float* w1  = (const float*)d_in[10];
    const float* bb1 = (const float*)d_in[11];
    const float* w2  = (const float*)d_in[12];
    const float* bb2 = (const float*)d_in[13];
    float* out = (float*)d_out;

    float *z, *y, *q, *k, *v, *s, *h, *o, *nll;
    float *wq_r, *wk_r, *wv_r, *w1_r, *w2_r, *enc_r;
    cudaGetSymbolAddress((void**)&z,   g_z);
    cudaGetSymbolAddress((void**)&y,   g_y);
    cudaGetSymbolAddress((void**)&q,   g_q);
    cudaGetSymbolAddress((void**)&k,   g_k);
    cudaGetSymbolAddress((void**)&v,   g_v);
    cudaGetSymbolAddress((void**)&s,   g_s);
    cudaGetSymbolAddress((void**)&h,   g_h);
    cudaGetSymbolAddress((void**)&o,   g_o);
    cudaGetSymbolAddress((void**)&nll, g_nll);
    cudaGetSymbolAddress((void**)&wq_r, g_wq_r);
    cudaGetSymbolAddress((void**)&wk_r, g_wk_r);
    cudaGetSymbolAddress((void**)&wv_r, g_wv_r);
    cudaGetSymbolAddress((void**)&w1_r, g_w1_r);
    cudaGetSymbolAddress((void**)&w2_r, g_w2_r);
    cudaGetSymbolAddress((void**)&enc_r, g_enc_r);

    // allow >48KB dynamic smem on all GEMM instantiations
    cudaFuncSetAttribute(tgemm<false,false,false,false,true>,
        cudaFuncAttributeMaxDynamicSharedMemorySize, GEMM_SMEM_BYTES);
    cudaFuncSetAttribute(tgemm<true,false,false,false,false>,
        cudaFuncAttributeMaxDynamicSharedMemorySize, GEMM_SMEM_BYTES);
    cudaFuncSetAttribute(tgemm<false,false,false,false,false>,
        cudaFuncAttributeMaxDynamicSharedMemorySize, GEMM_SMEM_BYTES);
    cudaFuncSetAttribute(tgemm<false,true,true,false,true>,
        cudaFuncAttributeMaxDynamicSharedMemorySize, GEMM_SMEM_BYTES);
    cudaFuncSetAttribute(tgemm<false,true,false,true,false>,
        cudaFuncAttributeMaxDynamicSharedMemorySize, GEMM_SMEM_BYTES);

    const long long TD = (long long)SEQ_T * D_MODEL;
    const long long TT = (long long)SEQ_T * SEQ_T;
    const float attn_scale = 1.f / 32.f;
    const int WN = D_MODEL * D_MODEL / 1024;           // blocks for 1M elems

    // rounded operand copies (weights + tied decoder)
    round_kernel<<<WN, 256>>>(wq, wq_r);
    round_kernel<<<WN, 256>>>(wk, wk_r);
    round_kernel<<<WN, 256>>>(wv, wv_r);
    round_kernel<<<WN, 256>>>(w1, w1_r);
    round_kernel<<<WN, 256>>>(w2, w2_r);
    round_kernel<<<(int)((long long)VOCAB * D_MODEL / 1024), 256>>>(enc, enc_r);

    embed_kernel<<<ROWS, 256>>>(x, enc, z);

    const dim3 gMain(D_MODEL / 128, ROWS / 128);       // (8, 32)
    const dim3 gAttn(SEQ_T / 128, SEQ_T / 128, BATCH); // (8, 8, 4)

    for (int layer = 0; layer < NLAYERS; ++layer) {
        ln_kernel<<<ROWS, 256>>>(z, y, g1, b1);
        tgemm<false,false,false,false,true><<<gMain, 256, GEMM_SMEM_BYTES>>>(
            y, wq_r, q, nullptr, nullptr, ROWS, D_MODEL, D_MODEL, 1.f, 0, 0, 0);
        tgemm<false,false,false,false,true><<<gMain, 256, GEMM_SMEM_BYTES>>>(
            y, wk_r, k, nullptr, nullptr, ROWS, D_MODEL, D_MODEL, 1.f, 0, 0, 0);
        tgemm<false,false,false,false,true><<<gMain, 256, GEMM_SMEM_BYTES>>>(
            y, wv_r, v, nullptr, nullptr, ROWS, D_MODEL, D_MODEL, 1.f, 0, 0, 0);
        tgemm<true,false,false,false,false><<<gAttn, 256, GEMM_SMEM_BYTES>>>(
            q, k, s, nullptr, nullptr, SEQ_T, SEQ_T, D_MODEL, attn_scale, TD, TD, TT);
        softmax_kernel<<<ROWS, 256>>>(s);
        tgemm<false,false,false,false,false><<<gAttn, 256, GEMM_SMEM_BYTES>>>(
            s, v, o, nullptr, nullptr, SEQ_T, D_MODEL, SEQ_T, 1.f, TT, TD, TD);
        ln_kernel<<<ROWS, 256>>>(o, y, g2, b2);
        tgemm<false,true,true,false,true><<<gMain, 256, GEMM_SMEM_BYTES>>>(
            y, w1_r, h, bb1, nullptr, ROWS, D_MODEL, D_MODEL, 1.f, 0, 0, 0);
        tgemm<false,true,false,true,false><<<gMain, 256, GEMM_SMEM_BYTES>>>(
            h, w2_r, z, bb2, z, ROWS, D_MODEL, D_MODEL, 1.f, 0, 0, 0);
    }

    // rounded copy of z for the logits GEMM (residual z itself stays fp32)
    round_kernel<<<ROWS * D_MODEL / 1024, 256>>>(z, h);

    const dim3 gLog(VOCAB / 128, ROWS / 128);          // (250, 32)
    tgemm<true,false,false,false,false><<<gLog, 256, GEMM_SMEM_BYTES>>>(
        h, enc_r, out, nullptr, nullptr, ROWS, VOCAB, D_MODEL, 1.f, 0, 0, 0);

    nll_kernel<<<ROWS, 256>>>(out, ytk, nll);
    loss_kernel<<<1, 256>>>(nll, out, (long long)out_size);
}

// round 4
// speedup vs baseline: 3.5158x; 1.0147x over previous
#include <cuda_runtime.h>
#include <cuda_bf16.h>
#include <math.h>
#include <stdint.h>

// ---------------------------------------------------------------------------
// NanoGPT forward — round 4: tf32 mma.sync, 3-stage cp.async ring (1 sync/iter),
// in-GEMM tf32 conversion for the tied decoder (no enc rounding pass).
// ---------------------------------------------------------------------------

#define D_MODEL 1024
#define SEQ_T   1024
#define BATCH   4
#define ROWS    (BATCH * SEQ_T)
#define VOCAB   32000
#define NLAYERS 6
#define LOGITS_ELEMS ((long long)ROWS * VOCAB)

// ---- scratch ----
__device__ float g_z[ROWS * D_MODEL];
__device__ float g_y[ROWS * D_MODEL];
__device__ float g_q[ROWS * D_MODEL];
__device__ float g_k[ROWS * D_MODEL];
__device__ float g_v[ROWS * D_MODEL];
__device__ float g_s[BATCH * SEQ_T * SEQ_T];
__device__ float g_h[ROWS * D_MODEL];
__device__ float g_o[ROWS * D_MODEL];
__device__ float g_nll[ROWS];
__device__ float g_wq_r[D_MODEL * D_MODEL];
__device__ float g_wk_r[D_MODEL * D_MODEL];
__device__ float g_wv_r[D_MODEL * D_MODEL];
__device__ float g_w1_r[D_MODEL * D_MODEL];
__device__ float g_w2_r[D_MODEL * D_MODEL];

__device__ __forceinline__ float rnd_tf32(float x) {
    uint32_t u;
    asm("cvt.rna.tf32.f32 %0, %1;" : "=r"(u) : "f"(x));
    return __uint_as_float(u);
}
__device__ __forceinline__ uint32_t cvt_bits(uint32_t x) {
    uint32_t u;
    asm("cvt.rna.tf32.f32 %0, %1;" : "=r"(u) : "f"(__uint_as_float(x)));
    return u;
}

__device__ __forceinline__ void mma_tf32(float c[4], const uint32_t a[4],
                                         const uint32_t b[2]) {
    asm volatile(
        "mma.sync.aligned.m16n8k8.row.col.f32.tf32.tf32.f32 "
        "{%0,%1,%2,%3}, {%4,%5,%6,%7}, {%8,%9}, {%0,%1,%2,%3};\n"
        : "+f"(c[0]), "+f"(c[1]), "+f"(c[2]), "+f"(c[3])
        : "r"(a[0]), "r"(a[1]), "r"(a[2]), "r"(a[3]), "r"(b[0]), "r"(b[1]));
}

__device__ __forceinline__ void cpa16(float* dst, const float* src) {
    uint32_t d = (uint32_t)__cvta_generic_to_shared(dst);
    asm volatile("cp.async.cg.shared.global [%0], [%1], 16;\n"
                 :: "r"(d), "l"(src));
}

#define STAGES 3
#define STAGE_WORDS 9216               // A 128*36 + B 4608
#define GEMM_SMEM_BYTES (STAGES * STAGE_WORDS * 4)

// ---------------------------------------------------------------------------
// tf32 tensor GEMM. A must be pre-rounded tf32. B pre-rounded unless CVTB
// (then B fragments are rounded post-LDS).
//   TB=false: B KxN row-major.  TB=true: B NxK row-major (C = A B^T).
// Block 128x128x32, 256 thr, 8 warps (2m x 4n), warp tile 64x32.
// 3-stage cp.async ring, one __syncthreads per k-iter.
// ---------------------------------------------------------------------------
template <bool TB, bool BIAS, bool RELU, bool RES, bool ROUND, bool CVTB>
__global__ __launch_bounds__(256, 2)
void tgemm(const float* __restrict__ A, const float* __restrict__ B,
           float* __restrict__ C, const float* __restrict__ bias,
           const float* __restrict__ res,
           int M, int N, int K, float alpha,
           long long sA, long long sB, long long sC)
{
    extern __shared__ float smem[];

    A += (long long)blockIdx.z * sA;
    B += (long long)blockIdx.z * sB;
    C += (long long)blockIdx.z * sC;
    const float* resp = RES ? (res + (long long)blockIdx.z * sC) : nullptr;

    const int tid  = threadIdx.x;
    const int lane = tid & 31;
    const int warp = tid >> 5;
    const int wm   = (warp & 1) * 64;
    const int wn   = (warp >> 1) * 32;
    const int q    = lane & 3;
    const int g    = lane >> 2;
    const long long m0 = (long long)blockIdx.y * 128;
    const long long n0 = (long long)blockIdx.x * 128;

    const int arow = tid >> 3;          // +32*s
    const int ak4  = (tid & 7) * 4;
    const int bk   = tid >> 5;          // +8*s (NN)
    const int bn4  = (tid & 31) * 4;

    float acc[4][4][4];
#pragma unroll
    for (int mt = 0; mt < 4; ++mt)
#pragma unroll
        for (int nt = 0; nt < 4; ++nt)
#pragma unroll
            for (int i = 0; i < 4; ++i) acc[mt][nt][i] = 0.f;

    auto LOAD = [&](int stage, int k0) {
        float* As_ = smem + stage * STAGE_WORDS;
        float* Bs_ = As_ + 4608;
#pragma unroll
        for (int s = 0; s < 4; ++s)
            cpa16(&As_[(arow + 32 * s) * 36 + ak4],
                  A + (m0 + arow + 32 * s) * (long long)K + k0 + ak4);
        if (TB) {
#pragma unroll
            for (int s = 0; s < 4; ++s)
                cpa16(&Bs_[(arow + 32 * s) * 36 + ak4],
                      B + (n0 + arow + 32 * s) * (long long)K + k0 + ak4);
        } else {
#pragma unroll
            for (int s = 0; s < 4; ++s)
                cpa16(&Bs_[(bk + 8 * s) * 132 + bn4],
                      B + (long long)(k0 + bk + 8 * s) * N + n0 + bn4);
        }
    };

    auto COMP = [&](int stage) {
        const uint32_t* As_ = (const uint32_t*)(smem + stage * STAGE_WORDS);
        const uint32_t* Bs_ = As_ + 4608;
#pragma unroll
        for (int kb = 0; kb < 32; kb += 8) {
            uint32_t af[4][4], bf[4][2];
#pragma unroll
            for (int mt = 0; mt < 4; ++mt) {
                const int mr = wm + mt * 16 + g;
                af[mt][0] = As_[mr * 36 + kb + q];
                af[mt][1] = As_[(mr + 8) * 36 + kb + q];
                af[mt][2] = As_[mr * 36 + kb + q + 4];
                af[mt][3] = As_[(mr + 8) * 36 + kb + q + 4];
            }
#pragma unroll
            for (int nt = 0; nt < 4; ++nt) {
                const int nr = wn + nt * 8 + g;
                if (TB) {
                    bf[nt][0] = Bs_[nr * 36 + kb + q];
                    bf[nt][1] = Bs_[nr * 36 + kb + q + 4];
                } else {
                    bf[nt][0] = Bs_[(kb + q) * 132 + nr];
                    bf[nt][1] = Bs_[(kb + q + 4) * 132 + nr];
                }
                if (CVTB) {
                    bf[nt][0] = cvt_bits(bf[nt][0]);
                    bf[nt][1] = cvt_bits(bf[nt][1]);
                }
            }
#pragma unroll
            for (int mt = 0; mt < 4; ++mt)
#pragma unroll
                for (int nt = 0; nt < 4; ++nt)
                    mma_tf32(acc[mt][nt], af[mt], bf[nt]);
        }
    };

    const int T = K >> 5;
    LOAD(0, 0);
    asm volatile("cp.async.commit_group;\n");
    if (T > 1) LOAD(1, 32);
    asm volatile("cp.async.commit_group;\n");

    int st = 0;
    for (int i = 0; i < T; ++i) {
        asm volatile("cp.async.wait_group 1;\n");
        __syncthreads();
        if (i + 2 < T) {
            int ns = st + 2; if (ns >= STAGES) ns -= STAGES;
            LOAD(ns, (i + 2) << 5);
        }
        asm volatile("cp.async.commit_group;\n");
        COMP(st);
        if (++st == STAGES) st = 0;
    }

    // ---- epilogue ----
#pragma unroll
    for (int mt = 0; mt < 4; ++mt) {
        const long long r0 = m0 + wm + mt * 16 + g;
        const long long r1 = r0 + 8;
#pragma unroll
        for (int nt = 0; nt < 4; ++nt) {
            const long long col = n0 + wn + nt * 8 + 2 * q;
            float v0 = acc[mt][nt][0] * alpha;
            float v1 = acc[mt][nt][1] * alpha;
            float v2 = acc[mt][nt][2] * alpha;
            float v3 = acc[mt][nt][3] * alpha;
            if (BIAS) {
                const float bb0 = bias[col], bb1 = bias[col + 1];
                v0 += bb0; v1 += bb1; v2 += bb0; v3 += bb1;
            }
            if (RELU) {
                v0 = fmaxf(v0, 0.f); v1 = fmaxf(v1, 0.f);
                v2 = fmaxf(v2, 0.f); v3 = fmaxf(v3, 0.f);
            }
            if (RES) {
                const float2 q0 = *(const float2*)(resp + r0 * N + col);
                const float2 q1 = *(const float2*)(resp + r1 * N + col);
                v0 += q0.x; v1 += q0.y; v2 += q1.x; v3 += q1.y;
            }
            if (ROUND) {
                v0 = rnd_tf32(v0); v1 = rnd_tf32(v1);
                v2 = rnd_tf32(v2); v3 = rnd_tf32(v3);
            }
            *(float2*)(C + r0 * N + col) = make_float2(v0, v1);
            *(float2*)(C + r1 * N + col) = make_float2(v2, v3);
        }
    }
}

// ---------------------------------------------------------------------------
__global__ __launch_bounds__(256)
void round_kernel(const float* __restrict__ in, float* __restrict__ out)
{
    const long long i = ((long long)blockIdx.x * 256 + threadIdx.x) * 4;
    float4 v = *(const float4*)(in + i);
    v.x = rnd_tf32(v.x); v.y = rnd_tf32(v.y);
    v.z = rnd_tf32(v.z); v.w = rnd_tf32(v.w);
    *(float4*)(out + i) = v;
}

__global__ __launch_bounds__(256)
void embed_kernel(const int* __restrict__ x, const float* __restrict__ enc,
                  float* __restrict__ z)
{
    const int row = blockIdx.x;
    const float4* s = (const float4*)(enc + (long long)x[row] * D_MODEL);
    float4* d = (float4*)(z + (long long)row * D_MODEL);
    d[threadIdx.x] = s[threadIdx.x];
}

// "LayerNorm" (faithful buggy): y = (x - mu/sqrt(var)) * g + b, ddof=1
__global__ __launch_bounds__(256)
void ln_kernel(const float* __restrict__ x, float* __restrict__ y,
               const float* __restrict__ g, const float* __restrict__ b)
{
    const int row = blockIdx.x;
    const float* xr = x + (long long)row * D_MODEL;
    float* yr = y + (long long)row * D_MODEL;

    float v[4];
    float s = 0.f, s2 = 0.f;
#pragma unroll
    for (int u = 0; u < 4; ++u) {
        v[u] = xr[threadIdx.x + u * 256];
        s += v[u];
        s2 += v[u] * v[u];
    }
#pragma unroll
    for (int o = 16; o; o >>= 1) {
        s  += __shfl_down_sync(0xffffffffu, s, o);
        s2 += __shfl_down_sync(0xffffffffu, s2, o);
    }
    __shared__ float shs[8], shs2[8], shsub;
    const int w = threadIdx.x >> 5, l = threadIdx.x & 31;
    if (l == 0) { shs[w] = s; shs2[w] = s2; }
    __syncthreads();
    if (threadIdx.x == 0) {
        float ts = 0.f, ts2 = 0.f;
#pragma unroll
        for (int i = 0; i < 8; ++i) { ts += shs[i]; ts2 += shs2[i]; }
        const float mu  = ts / (float)D_MODEL;
        const float var = (ts2 - (float)D_MODEL * mu * mu) / (float)(D_MODEL - 1);
        shsub = mu * rsqrtf(var);
    }
    __syncthreads();
    const float sub = shsub;
#pragma unroll
    for (int u = 0; u < 4; ++u) {
        const int i = threadIdx.x + u * 256;
        yr[i] = rnd_tf32((v[u] - sub) * g[i] + b[i]);
    }
}

__global__ __launch_bounds__(256)
void softmax_kernel(float* __restrict__ s)
{
    float* r = s + (long long)blockIdx.x * SEQ_T;
    float v[4];
    float m = -1e30f;
#pragma unroll
    for (int u = 0; u < 4; ++u) { v[u] = r[threadIdx.x + u * 256]; m = fmaxf(m, v[u]); }
#pragma unroll
    for (int o = 16; o; o >>= 1) m = fmaxf(m, __shfl_down_sync(0xffffffffu, m, o));
    __shared__ float shm[8], shsum[8], shM, shS;
    const int w = threadIdx.x >> 5, l = threadIdx.x & 31;
    if (l == 0) shm[w] = m;
    __syncthreads();
    if (threadIdx.x == 0) {
        float t = shm[0];
#pragma unroll
        for (int i = 1; i < 8; ++i) t = fmaxf(t, shm[i]);
        shM = t;
    }
    __syncthreads();
    const float M = shM;
    float sum = 0.f;
#pragma unroll
    for (int u = 0; u < 4; ++u) { v[u] = __expf(v[u] - M); sum += v[u]; }
#pragma unroll
    for (int o = 16; o; o >>= 1) sum += __shfl_down_sync(0xffffffffu, sum, o);
    if (l == 0) shsum[w] = sum;
    __syncthreads();
    if (threadIdx.x == 0) {
        float t = 0.f;
#pragma unroll
        for (int i = 0; i < 8; ++i) t += shsum[i];
        shS = 1.f / t;
    }
    __syncthreads();
    const float inv = shS;
#pragma unroll
    for (int u = 0; u < 4; ++u)
        r[threadIdx.x + u * 256] = rnd_tf32(v[u] * inv);
}

__global__ __launch_bounds__(256)
void nll_kernel(const float* __restrict__ logits, const int* __restrict__ y,
                float* __restrict__ nll)
{
    const int row = blockIdx.x;
    const float* r = logits + (long long)row * VOCAB;
    float m = -1e30f;
    for (int i = threadIdx.x; i < VOCAB; i += 256) m = fmaxf(m, r[i]);
#pragma unroll
    for (int o = 16; o; o >>= 1) m = fmaxf(m, __shfl_down_sync(0xffffffffu, m, o));
    __shared__ float shm[8], shsum[8], shM;
    const int w = threadIdx.x >> 5, l = threadIdx.x & 31;
    if (l == 0) shm[w] = m;
    __syncthreads();
    if (threadIdx.x == 0) {
        float t = shm[0];
#pragma unroll
        for (int i = 1; i < 8; ++i) t = fmaxf(t, shm[i]);
        shM = t;
    }
    __syncthreads();
    const float M = shM;
    float sum = 0.f;
    for (int i = threadIdx.x; i < VOCAB; i += 256) sum += __expf(r[i] - M);
#pragma unroll
    for (int o = 16; o; o >>= 1) sum += __shfl_down_sync(0xffffffffu, sum, o);
    if (l == 0) shsum[w] = sum;
    __syncthreads();
    if (threadIdx.x == 0) {
        float t = 0.f;
#pragma unroll
        for (int i = 0; i < 8; ++i) t += shsum[i];
        nll[row] = logf(t) + M - r[y[row]];
    }
}

__global__ __launch_bounds__(256)
void loss_kernel(const float* __restrict__ nll, float* __restrict__ out,
                 long long out_elems)
{
    __shared__ float sh[256];
    float s = 0.f;
#pragma unroll
    for (int u = 0; u < ROWS / 256; ++u) s += nll[threadIdx.x + u * 256];
    sh[threadIdx.x] = s;
    __syncthreads();
    for (int stride = 128; stride > 0; stride >>= 1) {
        if (threadIdx.x < stride) sh[threadIdx.x] += sh[threadIdx.x + stride];
        __syncthreads();
    }
    if (threadIdx.x == 0 && out_elems > LOGITS_ELEMS)
        out[LOGITS_ELEMS] = sh[0] / (float)ROWS;
}

// ---------------------------------------------------------------------------
extern "C" void kernel_launch(void* const* d_in, const int* in_sizes, int n_in,
                              void* d_out, int out_size)
{
    const int*   x   = (const int*)  d_in[0];
    const int*   ytk = (const int*)  d_in[1];
    const float* enc = (const float*)d_in[2];
    const float* g1  = (const float*)d_in[3];
    const float* b1  = (const float*)d_in[4];
    const float* wq  = (const float*)d_in[5];
    const float* wk  = (const float*)d_in[6];
    const float* wv  = (const float*)d_in[7];
    const float* g2  = (const float*)d_in[8];
    const float* b2  = (const float*)d_in[9];
    const float* w1  = (const float*)d_in[10];
    const float* bb1 = (const float*)d_in[11];
    const float* w2  = (const float*)d_in[12];
    const float* bb2 = (const float*)d_in[13];
    float* out = (float*)d_out;

    float *z, *y, *q, *k, *v, *s, *h, *o, *nll;
    float *wq_r, *wk_r, *wv_r, *w1_r, *w2_r;
    cudaGetSymbolAddress((void**)&z,   g_z);
    cudaGetSymbolAddress((void**)&y,   g_y);
    cudaGetSymbolAddress((void**)&q,   g_q);
    cudaGetSymbolAddress((void**)&k,   g_k);
    cudaGetSymbolAddress((void**)&v,   g_v);
    cudaGetSymbolAddress((void**)&s,   g_s);
    cudaGetSymbolAddress((void**)&h,   g_h);
    cudaGetSymbolAddress((void**)&o,   g_o);
    cudaGetSymbolAddress((void**)&nll, g_nll);
    cudaGetSymbolAddress((void**)&wq_r, g_wq_r);
    cudaGetSymbolAddress((void**)&wk_r, g_wk_r);
    cudaGetSymbolAddress((void**)&wv_r, g_wv_r);
    cudaGetSymbolAddress((void**)&w1_r, g_w1_r);
    cudaGetSymbolAddress((void**)&w2_r, g_w2_r);

    cudaFuncSetAttribute(tgemm<false,false,false,false,true,false>,
        cudaFuncAttributeMaxDynamicSharedMemorySize, GEMM_SMEM_BYTES);
    cudaFuncSetAttribute(tgemm<true,false,false,false,false,false>,
        cudaFuncAttributeMaxDynamicSharedMemorySize, GEMM_SMEM_BYTES);
    cudaFuncSetAttribute(tgemm<false,false,false,false,false,false>,
        cudaFuncAttributeMaxDynamicSharedMemorySize, GEMM_SMEM_BYTES);
    cudaFuncSetAttribute(tgemm<false,true,true,false,true,false>,
        cudaFuncAttributeMaxDynamicSharedMemorySize, GEMM_SMEM_BYTES);
    cudaFuncSetAttribute(tgemm<false,true,false,true,false,false>,
        cudaFuncAttributeMaxDynamicSharedMemorySize, GEMM_SMEM_BYTES);
    cudaFuncSetAttribute(tgemm<false,true,false,true,true,false>,
        cudaFuncAttributeMaxDynamicSharedMemorySize, GEMM_SMEM_BYTES);
    cudaFuncSetAttribute(tgemm<true,false,false,false,false,true>,
        cudaFuncAttributeMaxDynamicSharedMemorySize, GEMM_SMEM_BYTES);

    const long long TD = (long long)SEQ_T * D_MODEL;
    const long long TT = (long long)SEQ_T * SEQ_T;
    const float attn_scale = 1.f / 32.f;
    const int WN = D_MODEL * D_MODEL / 1024;

    round_kernel<<<WN, 256>>>(wq, wq_r);
    round_kernel<<<WN, 256>>>(wk, wk_r);
    round_kernel<<<WN, 256>>>(wv, wv_r);
    round_kernel<<<WN, 256>>>(w1, w1_r);
    round_kernel<<<WN, 256>>>(w2, w2_r);

    embed_kernel<<<ROWS, 256>>>(x, enc, z);

    const dim3 gMain(D_MODEL / 128, ROWS / 128);       // (8, 32)
    const dim3 gAttn(SEQ_T / 128, SEQ_T / 128, BATCH); // (8, 8, 4)

    for (int layer = 0; layer < NLAYERS; ++layer) {
        ln_kernel<<<ROWS, 256>>>(z, y, g1, b1);
        tgemm<false,false,false,false,true,false><<<gMain, 256, GEMM_SMEM_BYTES>>>(
            y, wq_r, q, nullptr, nullptr, ROWS, D_MODEL, D_MODEL, 1.f, 0, 0, 0);
        tgemm<false,false,false,false,true,false><<<gMain, 256, GEMM_SMEM_BYTES>>>(
            y, wk_r, k, nullptr, nullptr, ROWS, D_MODEL, D_MODEL, 1.f, 0, 0, 0);
        tgemm<false,false,false,false,true,false><<<gMain, 256, GEMM_SMEM_BYTES>>>(
            y, wv_r, v, nullptr, nullptr, ROWS, D_MODEL, D_MODEL, 1.f, 0, 0, 0);
        tgemm<true,false,false,false,false,false><<<gAttn, 256, GEMM_SMEM_BYTES>>>(
            q, k, s, nullptr, nullptr, SEQ_T, SEQ_T, D_MODEL, attn_scale, TD, TD, TT);
        softmax_kernel<<<ROWS, 256>>>(s);
        tgemm<false,false,false,false,false,false><<<gAttn, 256, GEMM_SMEM_BYTES>>>(
            s, v, o, nullptr, nullptr, SEQ_T, D_MODEL, SEQ_T, 1.f, TT, TD, TD);
        ln_kernel<<<ROWS, 256>>>(o, y, g2, b2);
        tgemm<false,true,true,false,true,false><<<gMain, 256, GEMM_SMEM_BYTES>>>(
            y, w1_r, h, bb1, nullptr, ROWS, D_MODEL, D_MODEL, 1.f, 0, 0, 0);
        if (layer < NLAYERS - 1) {
            tgemm<false,true,false,true,false,false><<<gMain, 256, GEMM_SMEM_BYTES>>>(
                h, w2_r, z, bb2, z, ROWS, D_MODEL, D_MODEL, 1.f, 0, 0, 0);
        } else {
            // final layer: rounded residual straight into h (logits A operand)
            tgemm<false,true,false,true,true,false><<<gMain, 256, GEMM_SMEM_BYTES>>>(
                h, w2_r, y, bb2, z, ROWS, D_MODEL, D_MODEL, 1.f, 0, 0, 0);
        }
    }

    // logits = round(z) @ enc^T, enc converted in-GEMM (CVTB)
    const dim3 gLog(VOCAB / 128, ROWS / 128);          // (250, 32)
    tgemm<true,false,false,false,false,true><<<gLog, 256, GEMM_SMEM_BYTES>>>(
        y, enc, out, nullptr, nullptr, ROWS, VOCAB, D_MODEL, 1.f, 0, 0, 0);

    nll_kernel<<<ROWS, 256>>>(out, ytk, nll);
    loss_kernel<<<1, 256>>>(nll, out, (long long)out_size);
}

// round 7
// speedup vs baseline: 3.9062x; 1.1111x over previous
#include <cuda_runtime.h>
#include <math.h>
#include <stdint.h>

// ---------------------------------------------------------------------------
// NanoGPT forward — round 6: tf32 mma.sync + ldmatrix fragment feeding.
// All GEMMs NT (K-major x K-major); weights transpose-rounded per replay.
// (tcgen05 is unavailable: harness ptxas targets sm_103, not sm_103a.)
// ---------------------------------------------------------------------------

#define D_MODEL 1024
#define SEQ_T   1024
#define BATCH   4
#define ROWS    (BATCH * SEQ_T)
#define VOCAB   32000
#define NLAYERS 6
#define LOGITS_ELEMS ((long long)ROWS * VOCAB)

// ---- scratch ----
__device__ float g_z[ROWS * D_MODEL];
__device__ float g_y[ROWS * D_MODEL];
__device__ float g_q[ROWS * D_MODEL];
__device__ float g_k[ROWS * D_MODEL];
__device__ float g_vT[D_MODEL * ROWS];          // v transposed: [d][b*T+t]
__device__ float g_s[BATCH * SEQ_T * SEQ_T];
__device__ float g_h[ROWS * D_MODEL];
__device__ float g_o[ROWS * D_MODEL];
__device__ float g_nll[ROWS];
__device__ float g_wqT[D_MODEL * D_MODEL];
__device__ float g_wkT[D_MODEL * D_MODEL];
__device__ float g_wvT[D_MODEL * D_MODEL];
__device__ float g_w1T[D_MODEL * D_MODEL];
__device__ float g_w2T[D_MODEL * D_MODEL];
__device__ float g_enc_r[(long long)VOCAB * D_MODEL];

__device__ __forceinline__ float rnd_tf32(float x) {
    uint32_t u;
    asm("cvt.rna.tf32.f32 %0, %1;" : "=r"(u) : "f"(x));
    return __uint_as_float(u);
}

__device__ __forceinline__ void mma_tf32(float c[4], const uint32_t a[4],
                                         const uint32_t b[2]) {
    asm volatile(
        "mma.sync.aligned.m16n8k8.row.col.f32.tf32.tf32.f32 "
        "{%0,%1,%2,%3}, {%4,%5,%6,%7}, {%8,%9}, {%0,%1,%2,%3};\n"
        : "+f"(c[0]), "+f"(c[1]), "+f"(c[2]), "+f"(c[3])
        : "r"(a[0]), "r"(a[1]), "r"(a[2]), "r"(a[3]), "r"(b[0]), "r"(b[1]));
}

__device__ __forceinline__ void ldsm4(uint32_t r[4], uint32_t addr) {
    asm volatile("ldmatrix.sync.aligned.m8n8.x4.shared.b16 {%0,%1,%2,%3}, [%4];"
                 : "=r"(r[0]), "=r"(r[1]), "=r"(r[2]), "=r"(r[3]) : "r"(addr));
}

__device__ __forceinline__ void cpa16s(uint32_t saddr, const float* g) {
    asm volatile("cp.async.cg.shared.global [%0], [%1], 16;\n" :: "r"(saddr), "l"(g));
}

#define STAGES 3
#define STAGE_WORDS 9216                 // A 128*36 + B 128*36
#define TRANS_BUF_WORDS (128 * 136)      // 69632B transposed-epilogue buffer
#define GEMM_SMEM_BYTES (STAGES * STAGE_WORDS * 4 > TRANS_BUF_WORDS * 4 ? \
                         STAGES * STAGE_WORDS * 4 : TRANS_BUF_WORDS * 4)

// ---------------------------------------------------------------------------
// tf32 tensor GEMM, NT only: C[M,N] = alpha * A[M,K] @ B[N,K]^T.
// A ld=lda, B ld=ldb (both K-contiguous, pre-rounded tf32).
// Block 128x128x32, 256 thr, 8 warps (2m x 4n), warp tile 64x32.
// 3-stage cp.async ring; fragments via ldmatrix.x4 (24 LDSM + 64 HMMA /chunk).
// TRANS: writes C^T via smem-staged transpose (C[col][row], ld=ldc).
// ---------------------------------------------------------------------------
template <bool BIAS, bool RELU, bool RES, bool ROUND, bool TRANS>
__global__ __launch_bounds__(256, 2)
void tgemm(const float* __restrict__ A, const float* __restrict__ B,
           float* __restrict__ C, const float* __restrict__ bias,
           const float* __restrict__ res,
           int K, int lda, int ldb, int ldc, float alpha,
           long long sA, long long sB, long long sC)
{
    extern __shared__ float smem[];

    A += (long long)blockIdx.z * sA;
    B += (long long)blockIdx.z * sB;
    C += (long long)blockIdx.z * sC;
    const float* resp = RES ? (res + (long long)blockIdx.z * sC) : nullptr;

    const int tid  = threadIdx.x;
    const int lane = tid & 31;
    const int warp = tid >> 5;
    const int wm   = (warp & 1) * 64;
    const int wn   = (warp >> 1) * 32;
    const int q    = lane & 3;
    const int g    = lane >> 2;
    const long long m0 = (long long)blockIdx.y * 128;
    const long long n0 = (long long)blockIdx.x * 128;

    const uint32_t smem_u = (uint32_t)__cvta_generic_to_shared(smem);

    // producer map: 4 rows of A + 4 rows of B per thread (float4 chunks)
    const int prow = tid >> 3;          // +32*s
    const int pk4  = (tid & 7) * 4;

    // ldmatrix per-lane word offsets (within a stage)
    const uint32_t aw = (uint32_t)((wm + (lane & 15)) * 36 + ((lane >> 4) & 1) * 4);
    const uint32_t bw = (uint32_t)(4608 +
        (wn + ((lane >> 4) & 1) * 8 + (lane & 7)) * 36 + ((lane >> 3) & 1) * 4);

    float acc[4][4][4];
#pragma unroll
    for (int mt = 0; mt < 4; ++mt)
#pragma unroll
        for (int nt = 0; nt < 4; ++nt)
#pragma unroll
            for (int i = 0; i < 4; ++i) acc[mt][nt][i] = 0.f;

    auto LOAD = [&](int stage, int k0) {
        const uint32_t sb = smem_u + stage * (STAGE_WORDS * 4);
#pragma unroll
        for (int s = 0; s < 4; ++s)
            cpa16s(sb + ((prow + 32 * s) * 36 + pk4) * 4,
                   A + (m0 + prow + 32 * s) * (long long)lda + k0 + pk4);
#pragma unroll
        for (int s = 0; s < 4; ++s)
            cpa16s(sb + (4608 + (prow + 32 * s) * 36 + pk4) * 4,
                   B + (n0 + prow + 32 * s) * (long long)ldb + k0 + pk4);
    };

    auto COMP = [&](int stage) {
        const uint32_t sb = smem_u + stage * (STAGE_WORDS * 4);
#pragma unroll
        for (int kb = 0; kb < 4; ++kb) {
            uint32_t af[4][4], bf[4][2];
#pragma unroll
            for (int mt = 0; mt < 4; ++mt)
                ldsm4(af[mt], sb + (aw + mt * 576 + kb * 8) * 4);
#pragma unroll
            for (int tp = 0; tp < 2; ++tp) {
                uint32_t r[4];
                ldsm4(r, sb + (bw + tp * 576 + kb * 8) * 4);
                bf[tp * 2][0] = r[0]; bf[tp * 2][1] = r[1];
                bf[tp * 2 + 1][0] = r[2]; bf[tp * 2 + 1][1] = r[3];
            }
#pragma unroll
            for (int mt = 0; mt < 4; ++mt)
#pragma unroll
                for (int nt = 0; nt < 4; ++nt)
                    mma_tf32(acc[mt][nt], af[mt], bf[nt]);
        }
    };

    const int T = K >> 5;
    LOAD(0, 0);
    asm volatile("cp.async.commit_group;\n");
    if (T > 1) LOAD(1, 32);
    asm volatile("cp.async.commit_group;\n");

    int st = 0;
    for (int i = 0; i < T; ++i) {
        asm volatile("cp.async.wait_group 1;\n");
        __syncthreads();
        if (i + 2 < T) {
            int ns = st + 2; if (ns >= STAGES) ns -= STAGES;
            LOAD(ns, (i + 2) << 5);
        }
        asm volatile("cp.async.commit_group;\n");
        COMP(st);
        if (++st == STAGES) st = 0;
    }

    // ---- epilogue ----
    if (!TRANS) {
#pragma unroll
        for (int mt = 0; mt < 4; ++mt) {
            const long long r0 = m0 + wm + mt * 16 + g;
            const long long r1 = r0 + 8;
#pragma unroll
            for (int nt = 0; nt < 4; ++nt) {
                const long long col = n0 + wn + nt * 8 + 2 * q;
                float v0 = acc[mt][nt][0] * alpha;
                float v1 = acc[mt][nt][1] * alpha;
                float v2 = acc[mt][nt][2] * alpha;
                float v3 = acc[mt][nt][3] * alpha;
                if (BIAS) {
                    const float bb0 = bias[col], bb1 = bias[col + 1];
                    v0 += bb0; v1 += bb1; v2 += bb0; v3 += bb1;
                }
                if (RELU) {
                    v0 = fmaxf(v0, 0.f); v1 = fmaxf(v1, 0.f);
                    v2 = fmaxf(v2, 0.f); v3 = fmaxf(v3, 0.f);
                }
                if (RES) {
                    const float2 q0 = *(const float2*)(resp + r0 * ldc + col);
                    const float2 q1 = *(const float2*)(resp + r1 * ldc + col);
                    v0 += q0.x; v1 += q0.y; v2 += q1.x; v3 += q1.y;
                }
                if (ROUND) {
                    v0 = rnd_tf32(v0); v1 = rnd_tf32(v1);
                    v2 = rnd_tf32(v2); v3 = rnd_tf32(v3);
                }
                *(float2*)(C + r0 * ldc + col) = make_float2(v0, v1);
                *(float2*)(C + r1 * ldc + col) = make_float2(v2, v3);
            }
        }
    } else {
        // stage into smem [128][136], then coalesced transposed store
        __syncthreads();   // cp.async buffers no longer needed
#pragma unroll
        for (int mt = 0; mt < 4; ++mt) {
            const int rl0 = wm + mt * 16 + g;
#pragma unroll
            for (int nt = 0; nt < 4; ++nt) {
                const int cl = wn + nt * 8 + 2 * q;
                *(float2*)&smem[rl0 * 136 + cl] =
                    make_float2(acc[mt][nt][0] * alpha, acc[mt][nt][1] * alpha);
                *(float2*)&smem[(rl0 + 8) * 136 + cl] =
                    make_float2(acc[mt][nt][2] * alpha, acc[mt][nt][3] * alpha);
            }
        }
        __syncthreads();
        const int col  = tid & 127;
        const int half = tid >> 7;          // 0/1 -> 64-row halves
        float* crow = C + (n0 + col) * (long long)ldc + m0 + half * 64;
#pragma unroll
        for (int j = 0; j < 16; ++j) {
            const int rb = half * 64 + j * 4;
            float4 v;
            v.x = smem[(rb + 0) * 136 + col];
            v.y = smem[(rb + 1) * 136 + col];
            v.z = smem[(rb + 2) * 136 + col];
            v.w = smem[(rb + 3) * 136 + col];
            if (ROUND) {
                v.x = rnd_tf32(v.x); v.y = rnd_tf32(v.y);
                v.z = rnd_tf32(v.z); v.w = rnd_tf32(v.w);
            }
            *(float4*)(crow + j * 4) = v;
        }
    }
}

// ---------------------------------------------------------------------------
// transpose + tf32-round: out[n][k] = rnd(in[k][n]), 1024x1024
// ---------------------------------------------------------------------------
__global__ __launch_bounds__(256)
void transpose_round(const float* __restrict__ in, float* __restrict__ out)
{
    __shared__ float t[32][33];
    const int tx = threadIdx.x & 31, ty = threadIdx.x >> 5;  // 32x8
    const int bx = blockIdx.x * 32, by = blockIdx.y * 32;
#pragma unroll
    for (int j = 0; j < 32; j += 8)
        t[ty + j][tx] = in[(long long)(by + ty + j) * D_MODEL + bx + tx];
    __syncthreads();
#pragma unroll
    for (int j = 0; j < 32; j += 8)
        out[(long long)(bx + ty + j) * D_MODEL + by + tx] = rnd_tf32(t[tx][ty + j]);
}

// tf32-round copy, high MLP (16 coalesced float4 per thread)
__global__ __launch_bounds__(256)
void round_copy(const float* __restrict__ in, float* __restrict__ out)
{
    const long long base = (long long)blockIdx.x * 4096;
#pragma unroll
    for (int j = 0; j < 16; ++j) {
        const long long i = (base + j * 256 + threadIdx.x) * 4;
        float4 v = *(const float4*)(in + i);
        v.x = rnd_tf32(v.x); v.y = rnd_tf32(v.y);
        v.z = rnd_tf32(v.z); v.w = rnd_tf32(v.w);
        *(float4*)(out + i) = v;
    }
}

__global__ __launch_bounds__(256)
void embed_kernel(const int* __restrict__ x, const float* __restrict__ enc,
                  float* __restrict__ z)
{
    const int row = blockIdx.x;
    const float4* s = (const float4*)(enc + (long long)x[row] * D_MODEL);
    float4* d = (float4*)(z + (long long)row * D_MODEL);
    d[threadIdx.x] = s[threadIdx.x];
}

// "LayerNorm" (faithful buggy): y = (x - mu/sqrt(var)) * g + b, ddof=1; tf32 out
__global__ __launch_bounds__(256)
void ln_kernel(const float* __restrict__ x, float* __restrict__ y,
               const float* __restrict__ g, const float* __restrict__ b)
{
    const int row = blockIdx.x;
    const float* xr = x + (long long)row * D_MODEL;
    float* yr = y + (long long)row * D_MODEL;
    float v[4];
    float s = 0.f, s2 = 0.f;
#pragma unroll
    for (int u = 0; u < 4; ++u) {
        v[u] = xr[threadIdx.x + u * 256];
        s += v[u]; s2 += v[u] * v[u];
    }
#pragma unroll
    for (int o = 16; o; o >>= 1) {
        s  += __shfl_down_sync(0xffffffffu, s, o);
        s2 += __shfl_down_sync(0xffffffffu, s2, o);
    }
    __shared__ float shs[8], shs2[8], shsub;
    const int w = threadIdx.x >> 5, l = threadIdx.x & 31;
    if (l == 0) { shs[w] = s; shs2[w] = s2; }
    __syncthreads();
    if (threadIdx.x == 0) {
        float ts = 0.f, ts2 = 0.f;
#pragma unroll
        for (int i = 0; i < 8; ++i) { ts += shs[i]; ts2 += shs2[i]; }
        const float mu  = ts / (float)D_MODEL;
        const float var = (ts2 - (float)D_MODEL * mu * mu) / (float)(D_MODEL - 1);
        shsub = mu * rsqrtf(var);
    }
    __syncthreads();
    const float sub = shsub;
#pragma unroll
    for (int u = 0; u < 4; ++u) {
        const int i = threadIdx.x + u * 256;
        yr[i] = rnd_tf32((v[u] - sub) * g[i] + b[i]);
    }
}

__global__ __launch_bounds__(256)
void softmax_kernel(float* __restrict__ s)
{
    float* r = s + (long long)blockIdx.x * SEQ_T;
    float v[4];
    float m = -1e30f;
#pragma unroll
    for (int u = 0; u < 4; ++u) { v[u] = r[threadIdx.x + u * 256]; m = fmaxf(m, v[u]); }
#pragma unroll
    for (int o = 16; o; o >>= 1) m = fmaxf(m, __shfl_down_sync(0xffffffffu, m, o));
    __shared__ float shm[8], shsum[8], shM, shS;
    const int w = threadIdx.x >> 5, l = threadIdx.x & 31;
    if (l == 0) shm[w] = m;
    __syncthreads();
    if (threadIdx.x == 0) {
        float t = shm[0];
#pragma unroll
        for (int i = 1; i < 8; ++i) t = fmaxf(t, shm[i]);
        shM = t;
    }
    __syncthreads();
    const float M = shM;
    float sum = 0.f;
#pragma unroll
    for (int u = 0; u < 4; ++u) { v[u] = __expf(v[u] - M); sum += v[u]; }
#pragma unroll
    for (int o = 16; o; o >>= 1) sum += __shfl_down_sync(0xffffffffu, sum, o);
    if (l == 0) shsum[w] = sum;
    __syncthreads();
    if (threadIdx.x == 0) {
        float t = 0.f;
#pragma unroll
        for (int i = 0; i < 8; ++i) t += shsum[i];
        shS = 1.f / t;
    }
    __syncthreads();
    const float inv = shS;
#pragma unroll
    for (int u = 0; u < 4; ++u)
        r[threadIdx.x + u * 256] = rnd_tf32(v[u] * inv);
}

// single-pass online logsumexp NLL
__global__ __launch_bounds__(256)
void nll_kernel(const float* __restrict__ logits, const int* __restrict__ y,
                float* __restrict__ nll)
{
    const int row = blockIdx.x;
    const float* r = logits + (long long)row * VOCAB;
    float m = -1e30f, s = 0.f;
    for (int i = threadIdx.x; i < VOCAB; i += 256) {
        const float v = r[i];
        if (v > m) { s = s * __expf(m - v) + 1.f; m = v; }
        else       { s += __expf(v - m); }
    }
#pragma unroll
    for (int o = 16; o; o >>= 1) {
        const float m2 = __shfl_down_sync(0xffffffffu, m, o);
        const float s2 = __shfl_down_sync(0xffffffffu, s, o);
        const float M = fmaxf(m, m2);
        s = s * __expf(m - M) + s2 * __expf(m2 - M);
        m = M;
    }
    __shared__ float shm[8], shs[8];
    const int w = threadIdx.x >> 5, l = threadIdx.x & 31;
    if (l == 0) { shm[w] = m; shs[w] = s; }
    __syncthreads();
    if (threadIdx.x == 0) {
        float M = shm[0], S = shs[0];
#pragma unroll
        for (int i = 1; i < 8; ++i) {
            const float MM = fmaxf(M, shm[i]);
            S = S * __expf(M - MM) + shs[i] * __expf(shm[i] - MM);
            M = MM;
        }
        nll[row] = logf(S) + M - r[y[row]];
    }
}

__global__ __launch_bounds__(256)
void loss_kernel(const float* __restrict__ nll, float* __restrict__ out,
                 long long out_elems)
{
    __shared__ float sh[256];
    float s = 0.f;
#pragma unroll
    for (int u = 0; u < ROWS / 256; ++u) s += nll[threadIdx.x + u * 256];
    sh[threadIdx.x] = s;
    __syncthreads();
    for (int stride = 128; stride > 0; stride >>= 1) {
        if (threadIdx.x < stride) sh[threadIdx.x] += sh[threadIdx.x + stride];
        __syncthreads();
    }
    if (threadIdx.x == 0 && out_elems > LOGITS_ELEMS)
        out[LOGITS_ELEMS] = sh[0] / (float)ROWS;
}

// ---------------------------------------------------------------------------
extern "C" void kernel_launch(void* const* d_in, const int* in_sizes, int n_in,
                              void* d_out, int out_size)
{
    const int*   x   = (const int*)  d_in[0];
    const int*   ytk = (const int*)  d_in[1];
    const float* enc = (const float*)d_in[2];
    const float* g1  = (const float*)d_in[3];
    const float* b1  = (const float*)d_in[4];
    const float* wq  = (const float*)d_in[5];
    const float* wk  = (const float*)d_in[6];
    const float* wv  = (const float*)d_in[7];
    const float* g2  = (const float*)d_in[8];
    const float* b2  = (const float*)d_in[9];
    const float* w1  = (const float*)d_in[10];
    const float* bb1 = (const float*)d_in[11];
    const float* w2  = (const float*)d_in[12];
    const float* bb2 = (const float*)d_in[13];
    float* out = (float*)d_out;

    float *z, *y, *q, *k, *vT, *s, *h, *o, *nll;
    float *wqT, *wkT, *wvT, *w1T, *w2T, *enc_r;
    cudaGetSymbolAddress((void**)&z,   g_z);
    cudaGetSymbolAddress((void**)&y,   g_y);
    cudaGetSymbolAddress((void**)&q,   g_q);
    cudaGetSymbolAddress((void**)&k,   g_k);
    cudaGetSymbolAddress((void**)&vT,  g_vT);
    cudaGetSymbolAddress((void**)&s,   g_s);
    cudaGetSymbolAddress((void**)&h,   g_h);
    cudaGetSymbolAddress((void**)&o,   g_o);
    cudaGetSymbolAddress((void**)&nll, g_nll);
    cudaGetSymbolAddress((void**)&wqT, g_wqT);
    cudaGetSymbolAddress((void**)&wkT, g_wkT);
    cudaGetSymbolAddress((void**)&wvT, g_wvT);
    cudaGetSymbolAddress((void**)&w1T, g_w1T);
    cudaGetSymbolAddress((void**)&w2T, g_w2T);
    cudaGetSymbolAddress((void**)&enc_r, g_enc_r);

    cudaFuncSetAttribute(tgemm<false,false,false,true,false>,
        cudaFuncAttributeMaxDynamicSharedMemorySize, GEMM_SMEM_BYTES);
    cudaFuncSetAttribute(tgemm<false,false,false,true,true>,
        cudaFuncAttributeMaxDynamicSharedMemorySize, GEMM_SMEM_BYTES);
    cudaFuncSetAttribute(tgemm<false,false,false,false,false>,
        cudaFuncAttributeMaxDynamicSharedMemorySize, GEMM_SMEM_BYTES);
    cudaFuncSetAttribute(tgemm<true,true,false,true,false>,
        cudaFuncAttributeMaxDynamicSharedMemorySize, GEMM_SMEM_BYTES);
    cudaFuncSetAttribute(tgemm<true,false,true,false,false>,
        cudaFuncAttributeMaxDynamicSharedMemorySize, GEMM_SMEM_BYTES);
    cudaFuncSetAttribute(tgemm<true,false,true,true,false>,
        cudaFuncAttributeMaxDynamicSharedMemorySize, GEMM_SMEM_BYTES);

    const long long TD = (long long)SEQ_T * D_MODEL;
    const long long TT = (long long)SEQ_T * SEQ_T;
    const float attn_scale = 1.f / 32.f;
    const int D = D_MODEL;

    const dim3 gT(32, 32);
    transpose_round<<<gT, 256>>>(wq, wqT);
    transpose_round<<<gT, 256>>>(wk, wkT);
    transpose_round<<<gT, 256>>>(wv, wvT);
    transpose_round<<<gT, 256>>>(w1, w1T);
    transpose_round<<<gT, 256>>>(w2, w2T);
    round_copy<<<(int)(((long long)VOCAB * D_MODEL) / 16384), 256>>>(enc, enc_r);

    embed_kernel<<<ROWS, 256>>>(x, enc, z);

    const dim3 gMain(D_MODEL / 128, ROWS / 128);        // (8, 32)
    const dim3 gAttn(SEQ_T / 128, SEQ_T / 128, BATCH);  // (8, 8, 4)

    for (int layer = 0; layer < NLAYERS; ++layer) {
        ln_kernel<<<ROWS, 256>>>(z, y, g1, b1);
        tgemm<false,false,false,true,false><<<gMain, 256, GEMM_SMEM_BYTES>>>(
            y, wqT, q, nullptr, nullptr, D, D, D, D, 1.f, 0, 0, 0);
        tgemm<false,false,false,true,false><<<gMain, 256, GEMM_SMEM_BYTES>>>(
            y, wkT, k, nullptr, nullptr, D, D, D, D, 1.f, 0, 0, 0);
        // vT[d][row] = (y @ wv)^T, rounded
        tgemm<false,false,false,true,true><<<gMain, 256, GEMM_SMEM_BYTES>>>(
            y, wvT, vT, nullptr, nullptr, D, D, D, ROWS, 1.f, 0, 0, 0);
        // s = q k^T / 32 per batch
        tgemm<false,false,false,false,false><<<gAttn, 256, GEMM_SMEM_BYTES>>>(
            q, k, s, nullptr, nullptr, D, D, D, SEQ_T, attn_scale, TD, TD, TT);
        softmax_kernel<<<ROWS, 256>>>(s);
        // o = s @ v : NT with B = vT batch slice (ld = ROWS)
        tgemm<false,false,false,false,false><<<gAttn, 256, GEMM_SMEM_BYTES>>>(
            s, vT, o, nullptr, nullptr, SEQ_T, SEQ_T, ROWS, D, 1.f, TT, SEQ_T, TD);
        ln_kernel<<<ROWS, 256>>>(o, y, g2, b2);
        tgemm<true,true,false,true,false><<<gMain, 256, GEMM_SMEM_BYTES>>>(
            y, w1T, h, bb1, nullptr, D, D, D, D, 1.f, 0, 0, 0);
        if (layer < NLAYERS - 1) {
            tgemm<true,false,true,false,false><<<gMain, 256, GEMM_SMEM_BYTES>>>(
                h, w2T, z, bb2, z, D, D, D, D, 1.f, 0, 0, 0);
        } else {
            // final layer: rounded residual into y (logits A operand)
            tgemm<true,false,true,true,false><<<gMain, 256, GEMM_SMEM_BYTES>>>(
                h, w2T, y, bb2, z, D, D, D, D, 1.f, 0, 0, 0);
        }
    }

    const dim3 gLog(VOCAB / 128, ROWS / 128);           // (250, 32)
    tgemm<false,false,false,false,false><<<gLog, 256, GEMM_SMEM_BYTES>>>(
        y, enc_r, out, nullptr, nullptr, D, D, D, VOCAB, 1.f, 0, 0, 0);

    nll_kernel<<<ROWS, 256>>>(out, ytk, nll);
    loss_kernel<<<1, 256>>>(nll, out, (long long)out_size);
}